// round 1
// baseline (speedup 1.0000x reference)
#include <cuda_runtime.h>
#include <math.h>

#define NV 100000
#define NF 200000
#define DD 512

// ---------------- scratch (device globals; no allocs allowed) ----------------
__device__ float g_P[(size_t)NV * DD];     // P = features @ W1 ; reused later as H3 (NF x 256, same size)
__device__ float g_H1[(size_t)NF * DD];    // relu(mean(P[faces]) + b1)
__device__ float g_H2[(size_t)NF * DD];    // relu(H1 @ W2 + b2)
__device__ float g_OUT12[(size_t)NF * 12];
__device__ float g_sums[NV * 3];
__device__ float g_cnt[NV];

__device__ __forceinline__ float4 zf4() { return make_float4(0.f, 0.f, 0.f, 0.f); }

// ---------------- fp32 SIMT GEMM: C[M,N] = A[M,K] @ B[K,N] (+bias, relu) ----
// BM=128, BN=64, BK=16, 256 threads, 8x4 per-thread microtile,
// register-prefetch double buffering (one __syncthreads per K-tile).
template<bool RELU, bool BIAS>
__device__ __forceinline__ void gemm_core(
    const float* __restrict__ A, const float* __restrict__ B,
    const float* __restrict__ bias, float* __restrict__ C,
    int M, int N, int K)
{
    __shared__ float As[2][16][132];
    __shared__ float Bs[2][16][64];

    const int tid = threadIdx.x;
    const int tx = tid & 15;        // 16 col groups
    const int ty = tid >> 4;        // 16 row groups
    const long brow = (long)blockIdx.y * 128;
    const long bcol = (long)blockIdx.x * 64;

    const int a_r = tid >> 2;       // 0..63 (and +64 for second half)
    const int a_k = (tid & 3) << 2; // 0,4,8,12
    const int b_k = tid >> 4;       // 0..15
    const int b_c = (tid & 15) << 2;

    const int nk = K >> 4;

    float4 ra0, ra1, rb;

    // prologue: load tile 0
    {
        long r0 = brow + a_r, r1 = r0 + 64;
        ra0 = (r0 < M) ? *(const float4*)(A + r0 * K + a_k) : zf4();
        ra1 = (r1 < M) ? *(const float4*)(A + r1 * K + a_k) : zf4();
        rb  = *(const float4*)(B + (long)b_k * N + bcol + b_c);
    }
    As[0][a_k + 0][a_r] = ra0.x; As[0][a_k + 1][a_r] = ra0.y;
    As[0][a_k + 2][a_r] = ra0.z; As[0][a_k + 3][a_r] = ra0.w;
    As[0][a_k + 0][a_r + 64] = ra1.x; As[0][a_k + 1][a_r + 64] = ra1.y;
    As[0][a_k + 2][a_r + 64] = ra1.z; As[0][a_k + 3][a_r + 64] = ra1.w;
    *(float4*)&Bs[0][b_k][b_c] = rb;
    __syncthreads();

    float acc[8][4];
#pragma unroll
    for (int i = 0; i < 8; i++)
#pragma unroll
        for (int j = 0; j < 4; j++) acc[i][j] = 0.f;

    for (int kt = 0; kt < nk; ++kt) {
        const int cur = kt & 1, nxt = cur ^ 1;
        if (kt + 1 < nk) {
            const int gk = (kt + 1) << 4;
            long r0 = brow + a_r, r1 = r0 + 64;
            ra0 = (r0 < M) ? *(const float4*)(A + r0 * K + gk + a_k) : zf4();
            ra1 = (r1 < M) ? *(const float4*)(A + r1 * K + gk + a_k) : zf4();
            rb  = *(const float4*)(B + (long)(gk + b_k) * N + bcol + b_c);
        }
#pragma unroll
        for (int k = 0; k < 16; k++) {
            float av[8], bv[4];
#pragma unroll
            for (int i = 0; i < 8; i++) av[i] = As[cur][k][ty * 8 + i];
#pragma unroll
            for (int j = 0; j < 4; j++) bv[j] = Bs[cur][k][tx * 4 + j];
#pragma unroll
            for (int i = 0; i < 8; i++)
#pragma unroll
                for (int j = 0; j < 4; j++) acc[i][j] = fmaf(av[i], bv[j], acc[i][j]);
        }
        if (kt + 1 < nk) {
            As[nxt][a_k + 0][a_r] = ra0.x; As[nxt][a_k + 1][a_r] = ra0.y;
            As[nxt][a_k + 2][a_r] = ra0.z; As[nxt][a_k + 3][a_r] = ra0.w;
            As[nxt][a_k + 0][a_r + 64] = ra1.x; As[nxt][a_k + 1][a_r + 64] = ra1.y;
            As[nxt][a_k + 2][a_r + 64] = ra1.z; As[nxt][a_k + 3][a_r + 64] = ra1.w;
            *(float4*)&Bs[nxt][b_k][b_c] = rb;
        }
        __syncthreads();
    }

#pragma unroll
    for (int i = 0; i < 8; i++) {
        long r = brow + ty * 8 + i;
        if (r < M) {
            float4 o;
            o.x = acc[i][0]; o.y = acc[i][1]; o.z = acc[i][2]; o.w = acc[i][3];
            if (BIAS) {
                float4 bb = *(const float4*)(bias + bcol + tx * 4);
                o.x += bb.x; o.y += bb.y; o.z += bb.z; o.w += bb.w;
            }
            if (RELU) {
                o.x = fmaxf(o.x, 0.f); o.y = fmaxf(o.y, 0.f);
                o.z = fmaxf(o.z, 0.f); o.w = fmaxf(o.w, 0.f);
            }
            *(float4*)(C + r * N + bcol + tx * 4) = o;
        }
    }
}

__global__ void __launch_bounds__(256) gemm1_kernel(const float* __restrict__ features,
                                                    const float* __restrict__ W1) {
    gemm_core<false, false>(features, W1, nullptr, g_P, NV, DD, DD);
}
__global__ void __launch_bounds__(256) gemm2_kernel(const float* __restrict__ W2,
                                                    const float* __restrict__ b2) {
    gemm_core<true, true>(g_H1, W2, b2, g_H2, NF, DD, DD);
}
__global__ void __launch_bounds__(256) gemm3_kernel(const float* __restrict__ W3,
                                                    const float* __restrict__ b3) {
    gemm_core<true, true>(g_H2, W3, b3, g_P /*H3*/, NF, 256, DD);
}

// ---------------- gather + mean + bias + relu (layer-1 epilogue) -------------
__global__ void __launch_bounds__(128) gather_mean_kernel(const int* __restrict__ faces,
                                                          const float* __restrict__ b1) {
    const int f = blockIdx.x;
    const int c4 = threadIdx.x; // 0..127 -> float4 columns of 512
    const int i0 = faces[f * 3 + 0];
    const int i1 = faces[f * 3 + 1];
    const int i2 = faces[f * 3 + 2];
    const float4* P4 = (const float4*)g_P;
    float4 v0 = P4[(size_t)i0 * 128 + c4];
    float4 v1 = P4[(size_t)i1 * 128 + c4];
    float4 v2 = P4[(size_t)i2 * 128 + c4];
    float4 bb = ((const float4*)b1)[c4];
    const float third = 1.f / 3.f;
    float4 o;
    o.x = fmaxf((v0.x + v1.x + v2.x) * third + bb.x, 0.f);
    o.y = fmaxf((v0.y + v1.y + v2.y) * third + bb.y, 0.f);
    o.z = fmaxf((v0.z + v1.z + v2.z) * third + bb.z, 0.f);
    o.w = fmaxf((v0.w + v1.w + v2.w) * third + bb.w, 0.f);
    ((float4*)g_H1)[(size_t)f * 128 + c4] = o;
}

// ---------------- head: OUT12 = H3 @ W4 + b4  (warp per row) -----------------
__global__ void __launch_bounds__(256) head_kernel(const float* __restrict__ W4,
                                                   const float* __restrict__ b4) {
    __shared__ float sW[256 * 12];
    __shared__ float sb[12];
    const int tid = threadIdx.x;
    for (int i = tid; i < 256 * 12; i += 256) sW[i] = W4[i];
    if (tid < 12) sb[tid] = b4[tid];
    __syncthreads();
    const int warp = tid >> 5, lane = tid & 31;
    const int row = blockIdx.x * 8 + warp;
    if (row >= NF) return;
    const float* h = g_P + (size_t)row * 256; // H3 lives in g_P
    float hr[8];
#pragma unroll
    for (int i = 0; i < 8; i++) hr[i] = h[lane + 32 * i];
    float acc[12];
#pragma unroll
    for (int c = 0; c < 12; c++) acc[c] = 0.f;
#pragma unroll
    for (int i = 0; i < 8; i++) {
        const float hv = hr[i];
        const float* w = &sW[(lane + 32 * i) * 12];
#pragma unroll
        for (int c = 0; c < 12; c++) acc[c] = fmaf(hv, w[c], acc[c]);
    }
#pragma unroll
    for (int off = 16; off > 0; off >>= 1)
#pragma unroll
        for (int c = 0; c < 12; c++) acc[c] += __shfl_down_sync(0xffffffffu, acc[c], off);
    if (lane == 0) {
        float* o = g_OUT12 + (size_t)row * 12;
#pragma unroll
        for (int c = 0; c < 12; c++) o[c] = acc[c] + sb[c];
    }
}

// ---------------- zero scratch accumulators ----------------------------------
__global__ void zero_kernel() {
    const int i = blockIdx.x * blockDim.x + threadIdx.x;
    if (i < NV * 3) g_sums[i] = 0.f;
    if (i < NV) g_cnt[i] = 0.f;
}

// ---------------- procrustes + transform + scatter ---------------------------
__device__ __forceinline__ void ortho_fallback(const float u[3], float o[3]) {
    const float ax = fabsf(u[0]), ay = fabsf(u[1]), az = fabsf(u[2]);
    float t0 = 0.f, t1 = 0.f, t2 = 0.f;
    if (ax <= ay && ax <= az) t0 = 1.f; else if (ay <= az) t1 = 1.f; else t2 = 1.f;
    const float d = t0 * u[0] + t1 * u[1] + t2 * u[2];
    o[0] = t0 - d * u[0]; o[1] = t1 - d * u[1]; o[2] = t2 - d * u[2];
    const float n = 1.f / sqrtf(o[0] * o[0] + o[1] * o[1] + o[2] * o[2]);
    o[0] *= n; o[1] *= n; o[2] *= n;
}

__global__ void __launch_bounds__(128) proc_kernel(
    const float* __restrict__ verts, const int* __restrict__ faces,
    float* __restrict__ out_tp, float* __restrict__ out_rot)
{
    const int f = blockIdx.x * 128 + threadIdx.x;
    if (f >= NF) return;
    const float* o = g_OUT12 + (size_t)f * 12;
    float m[3][3];
#pragma unroll
    for (int r = 0; r < 3; r++)
#pragma unroll
        for (int c = 0; c < 3; c++) m[r][c] = o[3 * r + c];
    const float tr0 = o[9], tr1 = o[10], tr2 = o[11];

    // B = M^T M (symmetric)
    float Aa[3][3];
#pragma unroll
    for (int i = 0; i < 3; i++)
#pragma unroll
        for (int j = 0; j < 3; j++)
            Aa[i][j] = m[0][i] * m[0][j] + m[1][i] * m[1][j] + m[2][i] * m[2][j];

    float Vm[3][3] = {{1.f, 0.f, 0.f}, {0.f, 1.f, 0.f}, {0.f, 0.f, 1.f}};
    const int PP[3] = {0, 0, 1};
    const int QQ[3] = {1, 2, 2};
    for (int sweep = 0; sweep < 8; ++sweep) {
#pragma unroll
        for (int pi = 0; pi < 3; ++pi) {
            const int p = PP[pi], q = QQ[pi];
            const float apq = Aa[p][q];
            if (fabsf(apq) < 1e-38f) continue;
            const float tau = (Aa[q][q] - Aa[p][p]) / (2.f * apq);
            const float tt = copysignf(1.f, tau) / (fabsf(tau) + sqrtf(1.f + tau * tau));
            const float cc = 1.f / sqrtf(1.f + tt * tt);
            const float ss = tt * cc;
#pragma unroll
            for (int r = 0; r < 3; r++) {
                const float arp = Aa[r][p], arq = Aa[r][q];
                Aa[r][p] = cc * arp - ss * arq; Aa[r][q] = ss * arp + cc * arq;
            }
#pragma unroll
            for (int r = 0; r < 3; r++) {
                const float apr = Aa[p][r], aqr = Aa[q][r];
                Aa[p][r] = cc * apr - ss * aqr; Aa[q][r] = ss * apr + cc * aqr;
            }
#pragma unroll
            for (int r = 0; r < 3; r++) {
                const float vrp = Vm[r][p], vrq = Vm[r][q];
                Vm[r][p] = cc * vrp - ss * vrq; Vm[r][q] = ss * vrp + cc * vrq;
            }
        }
    }

    // sort eigenvalues descending
    float dd[3] = {Aa[0][0], Aa[1][1], Aa[2][2]};
    int i0 = 0, i1 = 1, i2 = 2, tmp;
    if (dd[i0] < dd[i1]) { tmp = i0; i0 = i1; i1 = tmp; }
    if (dd[i0] < dd[i2]) { tmp = i0; i0 = i2; i2 = tmp; }
    if (dd[i1] < dd[i2]) { tmp = i1; i1 = i2; i2 = tmp; }
    const float v1[3] = {Vm[0][i0], Vm[1][i0], Vm[2][i0]};
    const float v2[3] = {Vm[0][i1], Vm[1][i1], Vm[2][i1]};
    const float v3[3] = {Vm[0][i2], Vm[1][i2], Vm[2][i2]};

    // s = det(V) snapped to +/-1
    const float cx = v2[1] * v3[2] - v2[2] * v3[1];
    const float cy = v2[2] * v3[0] - v2[0] * v3[2];
    const float cz = v2[0] * v3[1] - v2[1] * v3[0];
    float s = v1[0] * cx + v1[1] * cy + v1[2] * cz;
    s = (s >= 0.f) ? 1.f : -1.f;

    float u1[3], u2[3];
#pragma unroll
    for (int r = 0; r < 3; r++)
        u1[r] = m[r][0] * v1[0] + m[r][1] * v1[1] + m[r][2] * v1[2];
    const float n1 = sqrtf(u1[0] * u1[0] + u1[1] * u1[1] + u1[2] * u1[2]);
    if (n1 > 1e-30f) { const float inv = 1.f / n1; u1[0] *= inv; u1[1] *= inv; u1[2] *= inv; }
    else { u1[0] = 1.f; u1[1] = 0.f; u1[2] = 0.f; }
#pragma unroll
    for (int r = 0; r < 3; r++)
        u2[r] = m[r][0] * v2[0] + m[r][1] * v2[1] + m[r][2] * v2[2];
    const float dp = u2[0] * u1[0] + u2[1] * u1[1] + u2[2] * u1[2];
    u2[0] -= dp * u1[0]; u2[1] -= dp * u1[1]; u2[2] -= dp * u1[2];
    const float n2 = sqrtf(u2[0] * u2[0] + u2[1] * u2[1] + u2[2] * u2[2]);
    if (n2 > 1e-30f) { const float inv = 1.f / n2; u2[0] *= inv; u2[1] *= inv; u2[2] *= inv; }
    else ortho_fallback(u1, u2);
    const float u3[3] = {u1[1] * u2[2] - u1[2] * u2[1],
                         u1[2] * u2[0] - u1[0] * u2[2],
                         u1[0] * u2[1] - u1[1] * u2[0]};

    // R = u1 v1^T + u2 v2^T + s * u3 v3^T
    float R[3][3];
#pragma unroll
    for (int r = 0; r < 3; r++) {
        R[r][0] = u1[r] * v1[0] + u2[r] * v2[0] + s * u3[r] * v3[0];
        R[r][1] = u1[r] * v1[1] + u2[r] * v2[1] + s * u3[r] * v3[1];
        R[r][2] = u1[r] * v1[2] + u2[r] * v2[2] + s * u3[r] * v3[2];
    }

    float* rot = out_rot + (size_t)f * 9;
#pragma unroll
    for (int r = 0; r < 3; r++) {
        rot[3 * r + 0] = R[r][0]; rot[3 * r + 1] = R[r][1]; rot[3 * r + 2] = R[r][2];
    }

    float* tp = out_tp + (size_t)f * 9;
#pragma unroll
    for (int i = 0; i < 3; i++) {
        const int v = faces[f * 3 + i];
        const float px = verts[v * 3 + 0], py = verts[v * 3 + 1], pz = verts[v * 3 + 2];
        const float x = px * R[0][0] + py * R[1][0] + pz * R[2][0] + tr0;
        const float y = px * R[0][1] + py * R[1][1] + pz * R[2][1] + tr1;
        const float z = px * R[0][2] + py * R[1][2] + pz * R[2][2] + tr2;
        tp[3 * i + 0] = x; tp[3 * i + 1] = y; tp[3 * i + 2] = z;
        atomicAdd(&g_sums[v * 3 + 0], x);
        atomicAdd(&g_sums[v * 3 + 1], y);
        atomicAdd(&g_sums[v * 3 + 2], z);
        atomicAdd(&g_cnt[v], 1.f);
    }
}

// ---------------- finalize: vfeat = sums / clip(counts, 1) -------------------
__global__ void __launch_bounds__(128) finalize_kernel(float* __restrict__ out_feat) {
    const int v = blockIdx.x * 128 + threadIdx.x;
    if (v >= NV) return;
    const float inv = 1.f / fmaxf(g_cnt[v], 1.f);
    out_feat[v * 3 + 0] = g_sums[v * 3 + 0] * inv;
    out_feat[v * 3 + 1] = g_sums[v * 3 + 1] * inv;
    out_feat[v * 3 + 2] = g_sums[v * 3 + 2] * inv;
}

// ---------------- launch -----------------------------------------------------
extern "C" void kernel_launch(void* const* d_in, const int* in_sizes, int n_in,
                              void* d_out, int out_size) {
    const float* verts    = (const float*)d_in[0];
    const float* features = (const float*)d_in[1];
    const int*   faces    = (const int*)d_in[2];
    const float* W1 = (const float*)d_in[3];
    const float* b1 = (const float*)d_in[4];
    const float* W2 = (const float*)d_in[5];
    const float* b2 = (const float*)d_in[6];
    const float* W3 = (const float*)d_in[7];
    const float* b3 = (const float*)d_in[8];
    const float* W4 = (const float*)d_in[9];
    const float* b4 = (const float*)d_in[10];

    float* out = (float*)d_out;
    float* out_feat = out;                          // (1, NV, 3) -> NV*3
    float* out_tp   = out + (size_t)NV * 3;         // (NF, 3, 3) -> NF*9
    float* out_rot  = out_tp + (size_t)NF * 9;      // (NF, 3, 3) -> NF*9

    zero_kernel<<<(NV * 3 + 255) / 256, 256>>>();

    // P = features @ W1   (layer-1 hoisted to vertices: linear before bias/relu)
    gemm1_kernel<<<dim3(DD / 64, (NV + 127) / 128), 256>>>(features, W1);

    // H1 = relu(mean(P[faces]) + b1)
    gather_mean_kernel<<<NF, 128>>>(faces, b1);

    // H2 = relu(H1 @ W2 + b2)
    gemm2_kernel<<<dim3(DD / 64, (NF + 127) / 128), 256>>>(W2, b2);

    // H3 = relu(H2 @ W3 + b3)   (written into g_P)
    gemm3_kernel<<<dim3(256 / 64, (NF + 127) / 128), 256>>>(W3, b3);

    // OUT12 = H3 @ W4 + b4
    head_kernel<<<(NF + 7) / 8, 256>>>(W4, b4);

    // procrustes + transform + scatter-sum
    proc_kernel<<<(NF + 127) / 128, 128>>>(verts, faces, out_tp, out_rot);

    // vertex means
    finalize_kernel<<<(NV + 127) / 128, 128>>>(out_feat);
}

// round 4
// speedup vs baseline: 1.8651x; 1.8651x over previous
#include <cuda_runtime.h>
#include <cuda_bf16.h>
#include <math.h>
#include <stdint.h>

#define NV 100000
#define NF 200000
#define DD 512

// ---------------- scratch (device globals; no allocs allowed) ----------------
__device__ float g_P[(size_t)NV * DD];               // P = features@W1 (fp32); reused as H3 [NF,256] fp32
__device__ __nv_bfloat16 g_Fhi[(size_t)NV * DD];
__device__ __nv_bfloat16 g_Flo[(size_t)NV * DD];
__device__ __nv_bfloat16 g_H1hi[(size_t)NF * DD];
__device__ __nv_bfloat16 g_H1lo[(size_t)NF * DD];
__device__ __nv_bfloat16 g_H2hi[(size_t)NF * DD];
__device__ __nv_bfloat16 g_H2lo[(size_t)NF * DD];
__device__ __nv_bfloat16 g_Wt1hi[DD * DD], g_Wt1lo[DD * DD];   // [N,K] (transposed, K-major)
__device__ __nv_bfloat16 g_Wt2hi[DD * DD], g_Wt2lo[DD * DD];
__device__ __nv_bfloat16 g_Wt3hi[256 * DD], g_Wt3lo[256 * DD];
__device__ float g_OUT12[(size_t)NF * 12];
__device__ float g_sums[NV * 3];
__device__ float g_cnt[NV];

// ---------------- PTX helpers (arch-neutral: ldmatrix/mma.sync/cp.async) -----
static __device__ __forceinline__ uint32_t smem_u32(const void* p) {
    uint32_t a;
    asm("{ .reg .u64 t; cvta.to.shared.u64 t, %1; cvt.u32.u64 %0, t; }" : "=r"(a) : "l"(p));
    return a;
}

#define CP_ASYNC16(dst, src, sz) \
    asm volatile("cp.async.cg.shared.global [%0], [%1], 16, %2;" :: "r"(dst), "l"(src), "r"(sz))
#define CP_COMMIT() asm volatile("cp.async.commit_group;")
#define CP_WAIT1()  asm volatile("cp.async.wait_group 1;" ::: "memory")
#define CP_WAIT0()  asm volatile("cp.async.wait_group 0;" ::: "memory")

#define LDSM4(r, addr) \
    asm volatile("ldmatrix.sync.aligned.m8n8.x4.shared.b16 {%0,%1,%2,%3}, [%4];" \
        : "=r"((r)[0]), "=r"((r)[1]), "=r"((r)[2]), "=r"((r)[3]) : "r"(addr))

#define MMA16816(d, a, b0, b1) \
    asm volatile("mma.sync.aligned.m16n8k16.row.col.f32.bf16.bf16.f32 " \
        "{%0,%1,%2,%3}, {%4,%5,%6,%7}, {%8,%9}, {%0,%1,%2,%3};" \
        : "+f"((d)[0]), "+f"((d)[1]), "+f"((d)[2]), "+f"((d)[3]) \
        : "r"((a)[0]), "r"((a)[1]), "r"((a)[2]), "r"((a)[3]), "r"(b0), "r"(b1))

// ---------------- split-bf16 GEMM via mma.sync --------------------------------
// C[M,N] = (A_hi+A_lo)[M,K] @ (B_hi+B_lo)^T, B stored [N,K] K-major. K == 512.
// BM=128, BN=128, BK=32 bf16; 256 threads = 8 warps (4 m x 2 n); warp tile 32x64.
// Split: hi*hi + lo*hi + hi*lo (3 MMA terms).
// SMEM stage = A_hi(8K) A_lo(8K) B_hi(8K) B_lo(8K) = 32KB, double buffered = 64KB.
// Swizzle: within a 128-row x 64B tile, chunk' = chunk ^ ((row>>1)&3) (16B chunks).

#define STAGE_BYTES 32768
#define GSMEM_TOTAL (2 * STAGE_BYTES)

static __device__ __forceinline__ uint32_t sw_off(int r, int c) {
    return (uint32_t)(r * 64 + ((c ^ ((r >> 1) & 3)) << 4));
}

template<bool BIASRELU, bool SPLITOUT>
__global__ void __launch_bounds__(256) gemm_mma_kernel(
    const __nv_bfloat16* __restrict__ A_hi, const __nv_bfloat16* __restrict__ A_lo,
    const __nv_bfloat16* __restrict__ B_hi, const __nv_bfloat16* __restrict__ B_lo,
    const float* __restrict__ bias,
    float* __restrict__ Cf, __nv_bfloat16* __restrict__ Chi, __nv_bfloat16* __restrict__ Clo,
    int M, int N)
{
    extern __shared__ char smem[];
    __shared__ float sbias[128];
    const uint32_t smem_base = smem_u32(smem);
    const int tid = threadIdx.x;
    const int wid = tid >> 5;
    const int lane = tid & 31;
    const int wm = wid & 3;           // 4 warps along M
    const int wn = wid >> 2;          // 2 warps along N
    const long brow = (long)blockIdx.y * 128;
    const long bcol = (long)blockIdx.x * 128;
    const int K = DD;

    if (BIASRELU && tid < 128) sbias[tid] = bias[bcol + tid];

    // ---- stage loader (cp.async) ----
    auto load_stage = [&](int kt, int st) {
        const int kc = kt * 32;
        const uint32_t sb = smem_base + st * STAGE_BYTES;
#pragma unroll
        for (int i = 0; i < 2; i++) {
            const int idx = tid * 2 + i;      // 0..511
            const int r = idx >> 2, c = idx & 3;
            const uint32_t so = sw_off(r, c);
            const long ga = brow + r;
            const int okA = (ga < M) ? 16 : 0;
            const size_t eA = (size_t)(okA ? ga : 0) * K + kc + c * 8;
            CP_ASYNC16(sb + so,          A_hi + eA, okA);
            CP_ASYNC16(sb + 8192 + so,   A_lo + eA, okA);
            const size_t eB = (size_t)(bcol + r) * K + kc + c * 8;
            CP_ASYNC16(sb + 16384 + so,  B_hi + eB, 16);
            CP_ASYNC16(sb + 24576 + so,  B_lo + eB, 16);
        }
    };

    float acc[2][8][4];
#pragma unroll
    for (int mt = 0; mt < 2; mt++)
#pragma unroll
        for (int nt = 0; nt < 8; nt++)
#pragma unroll
            for (int j = 0; j < 4; j++) acc[mt][nt][j] = 0.f;

    load_stage(0, 0); CP_COMMIT();
    load_stage(1, 1); CP_COMMIT();

    const int NKT = K / 32;  // 16
    for (int kt = 0; kt < NKT; kt++) {
        if (kt == NKT - 1) { CP_WAIT0(); } else { CP_WAIT1(); }
        __syncthreads();
        const int st = kt & 1;
        const uint32_t sA_hi = smem_base + st * STAGE_BYTES;
        const uint32_t sA_lo = sA_hi + 8192;
        const uint32_t sB_hi = sA_hi + 16384;
        const uint32_t sB_lo = sA_hi + 24576;

#pragma unroll
        for (int ks = 0; ks < 2; ks++) {
            uint32_t ah[2][4], al[2][4], bh[4][4], bl[4][4];
#pragma unroll
            for (int mt = 0; mt < 2; mt++) {
                const int r = wm * 32 + mt * 16 + (lane & 15);
                const int c = ks * 2 + (lane >> 4);
                const uint32_t so = sw_off(r, c);
                LDSM4(ah[mt], sA_hi + so);
                LDSM4(al[mt], sA_lo + so);
            }
#pragma unroll
            for (int np = 0; np < 4; np++) {
                const int r = wn * 64 + np * 16 + (lane & 7) + (((lane >> 4) & 1) << 3);
                const int c = ks * 2 + ((lane >> 3) & 1);
                const uint32_t so = sw_off(r, c);
                LDSM4(bh[np], sB_hi + so);
                LDSM4(bl[np], sB_lo + so);
            }
#pragma unroll
            for (int mt = 0; mt < 2; mt++)
#pragma unroll
                for (int nt = 0; nt < 8; nt++) {
                    const uint32_t b0h = bh[nt >> 1][(nt & 1) * 2];
                    const uint32_t b1h = bh[nt >> 1][(nt & 1) * 2 + 1];
                    const uint32_t b0l = bl[nt >> 1][(nt & 1) * 2];
                    const uint32_t b1l = bl[nt >> 1][(nt & 1) * 2 + 1];
                    MMA16816(acc[mt][nt], ah[mt], b0h, b1h);
                    MMA16816(acc[mt][nt], al[mt], b0h, b1h);
                    MMA16816(acc[mt][nt], ah[mt], b0l, b1l);
                }
        }
        __syncthreads();
        if (kt + 2 < NKT) { load_stage(kt + 2, st); CP_COMMIT(); }
    }

    // ---- epilogue ----
#pragma unroll
    for (int mt = 0; mt < 2; mt++) {
        const long r0 = brow + wm * 32 + mt * 16 + (lane >> 2);
        const long r1 = r0 + 8;
#pragma unroll
        for (int nt = 0; nt < 8; nt++) {
            const int coll = wn * 64 + nt * 8 + (lane & 3) * 2;   // block-local col
            const long col = bcol + coll;
            float v00 = acc[mt][nt][0], v01 = acc[mt][nt][1];
            float v10 = acc[mt][nt][2], v11 = acc[mt][nt][3];
            if (BIASRELU) {
                const float bb0 = sbias[coll], bb1 = sbias[coll + 1];
                v00 = fmaxf(v00 + bb0, 0.f); v01 = fmaxf(v01 + bb1, 0.f);
                v10 = fmaxf(v10 + bb0, 0.f); v11 = fmaxf(v11 + bb1, 0.f);
            }
            if (SPLITOUT) {
                if (r0 < M) {
                    const __nv_bfloat16 h0 = __float2bfloat16(v00);
                    const __nv_bfloat16 h1 = __float2bfloat16(v01);
                    __nv_bfloat162 hp; hp.x = h0; hp.y = h1;
                    __nv_bfloat162 lp;
                    lp.x = __float2bfloat16(v00 - __bfloat162float(h0));
                    lp.y = __float2bfloat16(v01 - __bfloat162float(h1));
                    *(__nv_bfloat162*)(Chi + (size_t)r0 * N + col) = hp;
                    *(__nv_bfloat162*)(Clo + (size_t)r0 * N + col) = lp;
                }
                if (r1 < M) {
                    const __nv_bfloat16 h0 = __float2bfloat16(v10);
                    const __nv_bfloat16 h1 = __float2bfloat16(v11);
                    __nv_bfloat162 hp; hp.x = h0; hp.y = h1;
                    __nv_bfloat162 lp;
                    lp.x = __float2bfloat16(v10 - __bfloat162float(h0));
                    lp.y = __float2bfloat16(v11 - __bfloat162float(h1));
                    *(__nv_bfloat162*)(Chi + (size_t)r1 * N + col) = hp;
                    *(__nv_bfloat162*)(Clo + (size_t)r1 * N + col) = lp;
                }
            } else {
                if (r0 < M) { float2 o; o.x = v00; o.y = v01; *(float2*)(Cf + (size_t)r0 * N + col) = o; }
                if (r1 < M) { float2 o; o.x = v10; o.y = v11; *(float2*)(Cf + (size_t)r1 * N + col) = o; }
            }
        }
    }
}

// ---------------- prep kernels ------------------------------------------------
// W[K,N] (row-major) -> Th/Tl[N,K] bf16 hi/lo
__global__ void __launch_bounds__(256) transpose_split_kernel(
    const float* __restrict__ W, __nv_bfloat16* __restrict__ Th, __nv_bfloat16* __restrict__ Tl,
    int K, int N)
{
    __shared__ float tile[32][33];
    const int tx = threadIdx.x & 31, ty = threadIdx.x >> 5; // 32x8
    const int n0 = blockIdx.x * 32, k0 = blockIdx.y * 32;
    for (int dy = ty; dy < 32; dy += 8) {
        const int k = k0 + dy, n = n0 + tx;
        tile[dy][tx] = (k < K && n < N) ? W[(size_t)k * N + n] : 0.f;
    }
    __syncthreads();
    for (int dy = ty; dy < 32; dy += 8) {
        const int n = n0 + dy, k = k0 + tx;
        if (n < N && k < K) {
            const float v = tile[tx][dy];
            const __nv_bfloat16 h = __float2bfloat16(v);
            Th[(size_t)n * K + k] = h;
            Tl[(size_t)n * K + k] = __float2bfloat16(v - __bfloat162float(h));
        }
    }
}

__global__ void __launch_bounds__(256) split_feat_kernel(const float* __restrict__ F) {
    const size_t i = (size_t)blockIdx.x * 256 + threadIdx.x;
    if (i >= (size_t)NV * DD / 2) return;
    const float2 v = ((const float2*)F)[i];
    const __nv_bfloat16 h0 = __float2bfloat16(v.x);
    const __nv_bfloat16 h1 = __float2bfloat16(v.y);
    __nv_bfloat162 hp; hp.x = h0; hp.y = h1;
    __nv_bfloat162 lp;
    lp.x = __float2bfloat16(v.x - __bfloat162float(h0));
    lp.y = __float2bfloat16(v.y - __bfloat162float(h1));
    ((__nv_bfloat162*)g_Fhi)[i] = hp;
    ((__nv_bfloat162*)g_Flo)[i] = lp;
}

// ---------------- gather + mean + bias + relu -> H1 hi/lo --------------------
__global__ void __launch_bounds__(128) gather_mean_kernel(const int* __restrict__ faces,
                                                          const float* __restrict__ b1) {
    const int f = blockIdx.x;
    const int c4 = threadIdx.x;
    const int i0 = faces[f * 3 + 0];
    const int i1 = faces[f * 3 + 1];
    const int i2 = faces[f * 3 + 2];
    const float4* P4 = (const float4*)g_P;
    float4 v0 = P4[(size_t)i0 * 128 + c4];
    float4 v1 = P4[(size_t)i1 * 128 + c4];
    float4 v2 = P4[(size_t)i2 * 128 + c4];
    float4 bb = ((const float4*)b1)[c4];
    const float third = 1.f / 3.f;
    float o[4];
    o[0] = fmaxf((v0.x + v1.x + v2.x) * third + bb.x, 0.f);
    o[1] = fmaxf((v0.y + v1.y + v2.y) * third + bb.y, 0.f);
    o[2] = fmaxf((v0.z + v1.z + v2.z) * third + bb.z, 0.f);
    o[3] = fmaxf((v0.w + v1.w + v2.w) * third + bb.w, 0.f);
    __nv_bfloat16 h[4], l[4];
#pragma unroll
    for (int j = 0; j < 4; j++) {
        h[j] = __float2bfloat16(o[j]);
        l[j] = __float2bfloat16(o[j] - __bfloat162float(h[j]));
    }
    const size_t e = (size_t)f * DD + c4 * 4;
    __nv_bfloat162 hp0; hp0.x = h[0]; hp0.y = h[1];
    __nv_bfloat162 hp1; hp1.x = h[2]; hp1.y = h[3];
    __nv_bfloat162 lp0; lp0.x = l[0]; lp0.y = l[1];
    __nv_bfloat162 lp1; lp1.x = l[2]; lp1.y = l[3];
    *(__nv_bfloat162*)(g_H1hi + e) = hp0;
    *(__nv_bfloat162*)(g_H1hi + e + 2) = hp1;
    *(__nv_bfloat162*)(g_H1lo + e) = lp0;
    *(__nv_bfloat162*)(g_H1lo + e + 2) = lp1;
}

// ---------------- head: OUT12 = H3 @ W4 + b4  (warp per row) -----------------
__global__ void __launch_bounds__(256) head_kernel(const float* __restrict__ W4,
                                                   const float* __restrict__ b4) {
    __shared__ float sW[256 * 12];
    __shared__ float sb[12];
    const int tid = threadIdx.x;
    for (int i = tid; i < 256 * 12; i += 256) sW[i] = W4[i];
    if (tid < 12) sb[tid] = b4[tid];
    __syncthreads();
    const int warp = tid >> 5, lane = tid & 31;
    const int row = blockIdx.x * 8 + warp;
    if (row >= NF) return;
    const float* h = g_P + (size_t)row * 256;
    float hr[8];
#pragma unroll
    for (int i = 0; i < 8; i++) hr[i] = h[lane + 32 * i];
    float acc[12];
#pragma unroll
    for (int c = 0; c < 12; c++) acc[c] = 0.f;
#pragma unroll
    for (int i = 0; i < 8; i++) {
        const float hv = hr[i];
        const float* w = &sW[(lane + 32 * i) * 12];
#pragma unroll
        for (int c = 0; c < 12; c++) acc[c] = fmaf(hv, w[c], acc[c]);
    }
#pragma unroll
    for (int off = 16; off > 0; off >>= 1)
#pragma unroll
        for (int c = 0; c < 12; c++) acc[c] += __shfl_down_sync(0xffffffffu, acc[c], off);
    if (lane == 0) {
        float* o = g_OUT12 + (size_t)row * 12;
#pragma unroll
        for (int c = 0; c < 12; c++) o[c] = acc[c] + sb[c];
    }
}

__global__ void zero_kernel() {
    const int i = blockIdx.x * blockDim.x + threadIdx.x;
    if (i < NV * 3) g_sums[i] = 0.f;
    if (i < NV) g_cnt[i] = 0.f;
}

// ---------------- procrustes + transform + scatter ---------------------------
__device__ __forceinline__ void ortho_fallback(const float u[3], float o[3]) {
    const float ax = fabsf(u[0]), ay = fabsf(u[1]), az = fabsf(u[2]);
    float t0 = 0.f, t1 = 0.f, t2 = 0.f;
    if (ax <= ay && ax <= az) t0 = 1.f; else if (ay <= az) t1 = 1.f; else t2 = 1.f;
    const float d = t0 * u[0] + t1 * u[1] + t2 * u[2];
    o[0] = t0 - d * u[0]; o[1] = t1 - d * u[1]; o[2] = t2 - d * u[2];
    const float n = 1.f / sqrtf(o[0] * o[0] + o[1] * o[1] + o[2] * o[2]);
    o[0] *= n; o[1] *= n; o[2] *= n;
}

__global__ void __launch_bounds__(128) proc_kernel(
    const float* __restrict__ verts, const int* __restrict__ faces,
    float* __restrict__ out_tp, float* __restrict__ out_rot)
{
    const int f = blockIdx.x * 128 + threadIdx.x;
    if (f >= NF) return;
    const float* o = g_OUT12 + (size_t)f * 12;
    float m[3][3];
#pragma unroll
    for (int r = 0; r < 3; r++)
#pragma unroll
        for (int c = 0; c < 3; c++) m[r][c] = o[3 * r + c];
    const float tr0 = o[9], tr1 = o[10], tr2 = o[11];

    float Aa[3][3];
#pragma unroll
    for (int i = 0; i < 3; i++)
#pragma unroll
        for (int j = 0; j < 3; j++)
            Aa[i][j] = m[0][i] * m[0][j] + m[1][i] * m[1][j] + m[2][i] * m[2][j];

    float Vm[3][3] = {{1.f, 0.f, 0.f}, {0.f, 1.f, 0.f}, {0.f, 0.f, 1.f}};
    const int PP[3] = {0, 0, 1};
    const int QQ[3] = {1, 2, 2};
    for (int sweep = 0; sweep < 8; ++sweep) {
#pragma unroll
        for (int pi = 0; pi < 3; ++pi) {
            const int p = PP[pi], q = QQ[pi];
            const float apq = Aa[p][q];
            if (fabsf(apq) < 1e-38f) continue;
            const float tau = (Aa[q][q] - Aa[p][p]) / (2.f * apq);
            const float tt = copysignf(1.f, tau) / (fabsf(tau) + sqrtf(1.f + tau * tau));
            const float cc = 1.f / sqrtf(1.f + tt * tt);
            const float ss = tt * cc;
#pragma unroll
            for (int r = 0; r < 3; r++) {
                const float arp = Aa[r][p], arq = Aa[r][q];
                Aa[r][p] = cc * arp - ss * arq; Aa[r][q] = ss * arp + cc * arq;
            }
#pragma unroll
            for (int r = 0; r < 3; r++) {
                const float apr = Aa[p][r], aqr = Aa[q][r];
                Aa[p][r] = cc * apr - ss * aqr; Aa[q][r] = ss * apr + cc * aqr;
            }
#pragma unroll
            for (int r = 0; r < 3; r++) {
                const float vrp = Vm[r][p], vrq = Vm[r][q];
                Vm[r][p] = cc * vrp - ss * vrq; Vm[r][q] = ss * vrp + cc * vrq;
            }
        }
    }

    float dd[3] = {Aa[0][0], Aa[1][1], Aa[2][2]};
    int i0 = 0, i1 = 1, i2 = 2, tmp;
    if (dd[i0] < dd[i1]) { tmp = i0; i0 = i1; i1 = tmp; }
    if (dd[i0] < dd[i2]) { tmp = i0; i0 = i2; i2 = tmp; }
    if (dd[i1] < dd[i2]) { tmp = i1; i1 = i2; i2 = tmp; }
    const float v1[3] = {Vm[0][i0], Vm[1][i0], Vm[2][i0]};
    const float v2[3] = {Vm[0][i1], Vm[1][i1], Vm[2][i1]};
    const float v3[3] = {Vm[0][i2], Vm[1][i2], Vm[2][i2]};

    const float cx = v2[1] * v3[2] - v2[2] * v3[1];
    const float cy = v2[2] * v3[0] - v2[0] * v3[2];
    const float cz = v2[0] * v3[1] - v2[1] * v3[0];
    float s = v1[0] * cx + v1[1] * cy + v1[2] * cz;
    s = (s >= 0.f) ? 1.f : -1.f;

    float u1[3], u2[3];
#pragma unroll
    for (int r = 0; r < 3; r++)
        u1[r] = m[r][0] * v1[0] + m[r][1] * v1[1] + m[r][2] * v1[2];
    const float n1 = sqrtf(u1[0] * u1[0] + u1[1] * u1[1] + u1[2] * u1[2]);
    if (n1 > 1e-30f) { const float inv = 1.f / n1; u1[0] *= inv; u1[1] *= inv; u1[2] *= inv; }
    else { u1[0] = 1.f; u1[1] = 0.f; u1[2] = 0.f; }
#pragma unroll
    for (int r = 0; r < 3; r++)
        u2[r] = m[r][0] * v2[0] + m[r][1] * v2[1] + m[r][2] * v2[2];
    const float dp = u2[0] * u1[0] + u2[1] * u1[1] + u2[2] * u1[2];
    u2[0] -= dp * u1[0]; u2[1] -= dp * u1[1]; u2[2] -= dp * u1[2];
    const float n2 = sqrtf(u2[0] * u2[0] + u2[1] * u2[1] + u2[2] * u2[2]);
    if (n2 > 1e-30f) { const float inv = 1.f / n2; u2[0] *= inv; u2[1] *= inv; u2[2] *= inv; }
    else ortho_fallback(u1, u2);
    const float u3[3] = {u1[1] * u2[2] - u1[2] * u2[1],
                         u1[2] * u2[0] - u1[0] * u2[2],
                         u1[0] * u2[1] - u1[1] * u2[0]};

    float R[3][3];
#pragma unroll
    for (int r = 0; r < 3; r++) {
        R[r][0] = u1[r] * v1[0] + u2[r] * v2[0] + s * u3[r] * v3[0];
        R[r][1] = u1[r] * v1[1] + u2[r] * v2[1] + s * u3[r] * v3[1];
        R[r][2] = u1[r] * v1[2] + u2[r] * v2[2] + s * u3[r] * v3[2];
    }

    float* rot = out_rot + (size_t)f * 9;
#pragma unroll
    for (int r = 0; r < 3; r++) {
        rot[3 * r + 0] = R[r][0]; rot[3 * r + 1] = R[r][1]; rot[3 * r + 2] = R[r][2];
    }

    float* tp = out_tp + (size_t)f * 9;
#pragma unroll
    for (int i = 0; i < 3; i++) {
        const int v = faces[f * 3 + i];
        const float px = verts[v * 3 + 0], py = verts[v * 3 + 1], pz = verts[v * 3 + 2];
        const float x = px * R[0][0] + py * R[1][0] + pz * R[2][0] + tr0;
        const float y = px * R[0][1] + py * R[1][1] + pz * R[2][1] + tr1;
        const float z = px * R[0][2] + py * R[1][2] + pz * R[2][2] + tr2;
        tp[3 * i + 0] = x; tp[3 * i + 1] = y; tp[3 * i + 2] = z;
        atomicAdd(&g_sums[v * 3 + 0], x);
        atomicAdd(&g_sums[v * 3 + 1], y);
        atomicAdd(&g_sums[v * 3 + 2], z);
        atomicAdd(&g_cnt[v], 1.f);
    }
}

__global__ void __launch_bounds__(128) finalize_kernel(float* __restrict__ out_feat) {
    const int v = blockIdx.x * 128 + threadIdx.x;
    if (v >= NV) return;
    const float inv = 1.f / fmaxf(g_cnt[v], 1.f);
    out_feat[v * 3 + 0] = g_sums[v * 3 + 0] * inv;
    out_feat[v * 3 + 1] = g_sums[v * 3 + 1] * inv;
    out_feat[v * 3 + 2] = g_sums[v * 3 + 2] * inv;
}

// ---------------- launch -----------------------------------------------------
extern "C" void kernel_launch(void* const* d_in, const int* in_sizes, int n_in,
                              void* d_out, int out_size) {
    const float* verts    = (const float*)d_in[0];
    const float* features = (const float*)d_in[1];
    const int*   faces    = (const int*)d_in[2];
    const float* W1 = (const float*)d_in[3];
    const float* b1 = (const float*)d_in[4];
    const float* W2 = (const float*)d_in[5];
    const float* b2 = (const float*)d_in[6];
    const float* W3 = (const float*)d_in[7];
    const float* b3 = (const float*)d_in[8];
    const float* W4 = (const float*)d_in[9];
    const float* b4 = (const float*)d_in[10];

    float* out = (float*)d_out;
    float* out_feat = out;                          // (1, NV, 3)
    float* out_tp   = out + (size_t)NV * 3;         // (NF, 3, 3)
    float* out_rot  = out_tp + (size_t)NF * 9;      // (NF, 3, 3)

    static bool attr_done = false;
    if (!attr_done) {
        cudaFuncSetAttribute(gemm_mma_kernel<false, false>,
                             cudaFuncAttributeMaxDynamicSharedMemorySize, GSMEM_TOTAL);
        cudaFuncSetAttribute(gemm_mma_kernel<true, true>,
                             cudaFuncAttributeMaxDynamicSharedMemorySize, GSMEM_TOTAL);
        cudaFuncSetAttribute(gemm_mma_kernel<true, false>,
                             cudaFuncAttributeMaxDynamicSharedMemorySize, GSMEM_TOTAL);
        attr_done = true;
    }

    __nv_bfloat16 *Fhi, *Flo, *H1hi, *H1lo, *H2hi, *H2lo;
    __nv_bfloat16 *Wt1hi, *Wt1lo, *Wt2hi, *Wt2lo, *Wt3hi, *Wt3lo;
    float* Pp;
    cudaGetSymbolAddress((void**)&Fhi, g_Fhi);
    cudaGetSymbolAddress((void**)&Flo, g_Flo);
    cudaGetSymbolAddress((void**)&H1hi, g_H1hi);
    cudaGetSymbolAddress((void**)&H1lo, g_H1lo);
    cudaGetSymbolAddress((void**)&H2hi, g_H2hi);
    cudaGetSymbolAddress((void**)&H2lo, g_H2lo);
    cudaGetSymbolAddress((void**)&Wt1hi, g_Wt1hi);
    cudaGetSymbolAddress((void**)&Wt1lo, g_Wt1lo);
    cudaGetSymbolAddress((void**)&Wt2hi, g_Wt2hi);
    cudaGetSymbolAddress((void**)&Wt2lo, g_Wt2lo);
    cudaGetSymbolAddress((void**)&Wt3hi, g_Wt3hi);
    cudaGetSymbolAddress((void**)&Wt3lo, g_Wt3lo);
    cudaGetSymbolAddress((void**)&Pp, g_P);

    zero_kernel<<<(NV * 3 + 255) / 256, 256>>>();

    split_feat_kernel<<<(int)(((size_t)NV * DD / 2 + 255) / 256), 256>>>(features);
    transpose_split_kernel<<<dim3(512 / 32, 512 / 32), 256>>>(W1, Wt1hi, Wt1lo, 512, 512);
    transpose_split_kernel<<<dim3(512 / 32, 512 / 32), 256>>>(W2, Wt2hi, Wt2lo, 512, 512);
    transpose_split_kernel<<<dim3(256 / 32, 512 / 32), 256>>>(W3, Wt3hi, Wt3lo, 512, 256);

    // P = features @ W1 (fp32 out)
    gemm_mma_kernel<false, false><<<dim3(4, (NV + 127) / 128), 256, GSMEM_TOTAL>>>(
        Fhi, Flo, Wt1hi, Wt1lo, nullptr, Pp, nullptr, nullptr, NV, 512);

    // H1 = relu(mean(P[faces]) + b1) -> hi/lo
    gather_mean_kernel<<<NF, 128>>>(faces, b1);

    // H2 = relu(H1 @ W2 + b2) -> hi/lo
    gemm_mma_kernel<true, true><<<dim3(4, (NF + 127) / 128), 256, GSMEM_TOTAL>>>(
        H1hi, H1lo, Wt2hi, Wt2lo, b2, nullptr, H2hi, H2lo, NF, 512);

    // H3 = relu(H2 @ W3 + b3) -> fp32 into g_P
    gemm_mma_kernel<true, false><<<dim3(2, (NF + 127) / 128), 256, GSMEM_TOTAL>>>(
        H2hi, H2lo, Wt3hi, Wt3lo, b3, Pp, nullptr, nullptr, NF, 256);

    head_kernel<<<(NF + 7) / 8, 256>>>(W4, b4);
    proc_kernel<<<(NF + 127) / 128, 128>>>(verts, faces, out_tp, out_rot);
    finalize_kernel<<<(NV + 127) / 128, 128>>>(out_feat);
}

// round 5
// speedup vs baseline: 2.0711x; 1.1104x over previous
#include <cuda_runtime.h>
#include <cuda_bf16.h>
#include <math.h>
#include <stdint.h>

#define NV 100000
#define NF 200000
#define DD 512

// ---------------- scratch (device globals; no allocs allowed) ----------------
__device__ float g_P[(size_t)NV * DD];               // P = features@W1 (fp32); reused as H3 [NF,256] fp32
__device__ __nv_bfloat16 g_Fhi[(size_t)NV * DD];
__device__ __nv_bfloat16 g_Flo[(size_t)NV * DD];
__device__ __nv_bfloat16 g_H1hi[(size_t)NF * DD];
__device__ __nv_bfloat16 g_H1lo[(size_t)NF * DD];
__device__ __nv_bfloat16 g_H2hi[(size_t)NF * DD];
__device__ __nv_bfloat16 g_H2lo[(size_t)NF * DD];
__device__ __nv_bfloat16 g_Wt1hi[DD * DD], g_Wt1lo[DD * DD];   // [N,K] (transposed, K-major)
__device__ __nv_bfloat16 g_Wt2hi[DD * DD], g_Wt2lo[DD * DD];
__device__ __nv_bfloat16 g_Wt3hi[256 * DD], g_Wt3lo[256 * DD];
__device__ float g_OUT12[(size_t)NF * 12];
__device__ float g_sums[NV * 3];
__device__ float g_cnt[NV];

// ---------------- PTX helpers (arch-neutral: ldmatrix/mma.sync/cp.async) -----
static __device__ __forceinline__ uint32_t smem_u32(const void* p) {
    uint32_t a;
    asm("{ .reg .u64 t; cvta.to.shared.u64 t, %1; cvt.u32.u64 %0, t; }" : "=r"(a) : "l"(p));
    return a;
}

#define CP_ASYNC16(dst, src, sz) \
    asm volatile("cp.async.cg.shared.global [%0], [%1], 16, %2;" :: "r"(dst), "l"(src), "r"(sz))
#define CP_COMMIT() asm volatile("cp.async.commit_group;")
#define CP_WAIT2()  asm volatile("cp.async.wait_group 2;" ::: "memory")

#define LDSM4(r, addr) \
    asm volatile("ldmatrix.sync.aligned.m8n8.x4.shared.b16 {%0,%1,%2,%3}, [%4];" \
        : "=r"((r)[0]), "=r"((r)[1]), "=r"((r)[2]), "=r"((r)[3]) : "r"(addr))

#define MMA16816(d, a, b0, b1) \
    asm volatile("mma.sync.aligned.m16n8k16.row.col.f32.bf16.bf16.f32 " \
        "{%0,%1,%2,%3}, {%4,%5,%6,%7}, {%8,%9}, {%0,%1,%2,%3};" \
        : "+f"((d)[0]), "+f"((d)[1]), "+f"((d)[2]), "+f"((d)[3]) \
        : "r"((a)[0]), "r"((a)[1]), "r"((a)[2]), "r"((a)[3]), "r"(b0), "r"(b1))

// ---------------- split-bf16 GEMM via mma.sync --------------------------------
// C[M,N] = (A_hi+A_lo)[M,K] @ (B_hi+B_lo)^T, B stored [N,K] K-major. K in {512}.
// BM=128, BN=128, BK=32 bf16; 256 threads = 8 warps (4 m x 2 n); warp tile 32x64.
// Split: hi*hi + lo*hi + hi*lo (3 MMA terms).
// 4-stage cp.async pipeline, ONE __syncthreads per k-tile.
// Stage = A_hi(8K) A_lo(8K) B_hi(8K) B_lo(8K) = 32KB; 4 stages = 128KB.

#define NSTAGE 4
#define STAGE_BYTES 32768
#define GSMEM_TOTAL (NSTAGE * STAGE_BYTES)

static __device__ __forceinline__ uint32_t sw_off(int r, int c) {
    return (uint32_t)(r * 64 + ((c ^ ((r >> 1) & 3)) << 4));
}

template<bool BIASRELU, bool SPLITOUT>
__global__ void __launch_bounds__(256) gemm_mma_kernel(
    const __nv_bfloat16* __restrict__ A_hi, const __nv_bfloat16* __restrict__ A_lo,
    const __nv_bfloat16* __restrict__ B_hi, const __nv_bfloat16* __restrict__ B_lo,
    const float* __restrict__ bias,
    float* __restrict__ Cf, __nv_bfloat16* __restrict__ Chi, __nv_bfloat16* __restrict__ Clo,
    int M, int N)
{
    extern __shared__ char smem[];
    __shared__ float sbias[128];
    const uint32_t smem_base = smem_u32(smem);
    const int tid = threadIdx.x;
    const int wid = tid >> 5;
    const int lane = tid & 31;
    const int wm = wid & 3;           // 4 warps along M
    const int wn = wid >> 2;          // 2 warps along N
    const long brow = (long)blockIdx.y * 128;
    const long bcol = (long)blockIdx.x * 128;
    const int K = DD;

    if (BIASRELU && tid < 128) sbias[tid] = bias[bcol + tid];

    // ---- stage loader (cp.async) ----
    auto load_stage = [&](int kt, int st) {
        const int kc = kt * 32;
        const uint32_t sb = smem_base + st * STAGE_BYTES;
#pragma unroll
        for (int i = 0; i < 2; i++) {
            const int idx = tid * 2 + i;      // 0..511
            const int r = idx >> 2, c = idx & 3;
            const uint32_t so = sw_off(r, c);
            const long ga = brow + r;
            const int okA = (ga < M) ? 16 : 0;
            const size_t eA = (size_t)(okA ? ga : 0) * K + kc + c * 8;
            CP_ASYNC16(sb + so,          A_hi + eA, okA);
            CP_ASYNC16(sb + 8192 + so,   A_lo + eA, okA);
            const size_t eB = (size_t)(bcol + r) * K + kc + c * 8;
            CP_ASYNC16(sb + 16384 + so,  B_hi + eB, 16);
            CP_ASYNC16(sb + 24576 + so,  B_lo + eB, 16);
        }
    };

    float acc[2][8][4];
#pragma unroll
    for (int mt = 0; mt < 2; mt++)
#pragma unroll
        for (int nt = 0; nt < 8; nt++)
#pragma unroll
            for (int j = 0; j < 4; j++) acc[mt][nt][j] = 0.f;

    // prologue: 3 stages in flight
    load_stage(0, 0); CP_COMMIT();
    load_stage(1, 1); CP_COMMIT();
    load_stage(2, 2); CP_COMMIT();

    const int NKT = K / 32;  // 16
    for (int kt = 0; kt < NKT; kt++) {
        CP_WAIT2();              // all but 2 newest groups done -> stage kt resident
        __syncthreads();
        const int st = kt & (NSTAGE - 1);
        const uint32_t sA_hi = smem_base + st * STAGE_BYTES;
        const uint32_t sA_lo = sA_hi + 8192;
        const uint32_t sB_hi = sA_hi + 16384;
        const uint32_t sB_lo = sA_hi + 24576;

#pragma unroll
        for (int ks = 0; ks < 2; ks++) {
            uint32_t ah[2][4], al[2][4], bh[4][4], bl[4][4];
#pragma unroll
            for (int mt = 0; mt < 2; mt++) {
                const int r = wm * 32 + mt * 16 + (lane & 15);
                const int c = ks * 2 + (lane >> 4);
                const uint32_t so = sw_off(r, c);
                LDSM4(ah[mt], sA_hi + so);
                LDSM4(al[mt], sA_lo + so);
            }
#pragma unroll
            for (int np = 0; np < 4; np++) {
                const int r = wn * 64 + np * 16 + (lane & 7) + (((lane >> 4) & 1) << 3);
                const int c = ks * 2 + ((lane >> 3) & 1);
                const uint32_t so = sw_off(r, c);
                LDSM4(bh[np], sB_hi + so);
                LDSM4(bl[np], sB_lo + so);
            }
#pragma unroll
            for (int mt = 0; mt < 2; mt++)
#pragma unroll
                for (int nt = 0; nt < 8; nt++) {
                    const uint32_t b0h = bh[nt >> 1][(nt & 1) * 2];
                    const uint32_t b1h = bh[nt >> 1][(nt & 1) * 2 + 1];
                    const uint32_t b0l = bl[nt >> 1][(nt & 1) * 2];
                    const uint32_t b1l = bl[nt >> 1][(nt & 1) * 2 + 1];
                    MMA16816(acc[mt][nt], ah[mt], b0h, b1h);
                    MMA16816(acc[mt][nt], al[mt], b0h, b1h);
                    MMA16816(acc[mt][nt], ah[mt], b0l, b1l);
                }
        }
        // issue loads for stage kt+3 into slot (kt+3)%4 == (kt-1)%4 (safe: all
        // warps passed sync(kt), so compute(kt-1) on that slot is complete).
        if (kt + 3 < NKT) load_stage(kt + 3, (kt + 3) & (NSTAGE - 1));
        CP_COMMIT();             // commit every iteration keeps wait_group(2) exact
    }

    // ---- epilogue ----
#pragma unroll
    for (int mt = 0; mt < 2; mt++) {
        const long r0 = brow + wm * 32 + mt * 16 + (lane >> 2);
        const long r1 = r0 + 8;
#pragma unroll
        for (int nt = 0; nt < 8; nt++) {
            const int coll = wn * 64 + nt * 8 + (lane & 3) * 2;   // block-local col
            const long col = bcol + coll;
            float v00 = acc[mt][nt][0], v01 = acc[mt][nt][1];
            float v10 = acc[mt][nt][2], v11 = acc[mt][nt][3];
            if (BIASRELU) {
                const float bb0 = sbias[coll], bb1 = sbias[coll + 1];
                v00 = fmaxf(v00 + bb0, 0.f); v01 = fmaxf(v01 + bb1, 0.f);
                v10 = fmaxf(v10 + bb0, 0.f); v11 = fmaxf(v11 + bb1, 0.f);
            }
            if (SPLITOUT) {
                if (r0 < M) {
                    const __nv_bfloat16 h0 = __float2bfloat16(v00);
                    const __nv_bfloat16 h1 = __float2bfloat16(v01);
                    __nv_bfloat162 hp; hp.x = h0; hp.y = h1;
                    __nv_bfloat162 lp;
                    lp.x = __float2bfloat16(v00 - __bfloat162float(h0));
                    lp.y = __float2bfloat16(v01 - __bfloat162float(h1));
                    *(__nv_bfloat162*)(Chi + (size_t)r0 * N + col) = hp;
                    *(__nv_bfloat162*)(Clo + (size_t)r0 * N + col) = lp;
                }
                if (r1 < M) {
                    const __nv_bfloat16 h0 = __float2bfloat16(v10);
                    const __nv_bfloat16 h1 = __float2bfloat16(v11);
                    __nv_bfloat162 hp; hp.x = h0; hp.y = h1;
                    __nv_bfloat162 lp;
                    lp.x = __float2bfloat16(v10 - __bfloat162float(h0));
                    lp.y = __float2bfloat16(v11 - __bfloat162float(h1));
                    *(__nv_bfloat162*)(Chi + (size_t)r1 * N + col) = hp;
                    *(__nv_bfloat162*)(Clo + (size_t)r1 * N + col) = lp;
                }
            } else {
                if (r0 < M) { float2 o; o.x = v00; o.y = v01; *(float2*)(Cf + (size_t)r0 * N + col) = o; }
                if (r1 < M) { float2 o; o.x = v10; o.y = v11; *(float2*)(Cf + (size_t)r1 * N + col) = o; }
            }
        }
    }
}

// ---------------- prep kernels ------------------------------------------------
// W[K,N] (row-major) -> Th/Tl[N,K] bf16 hi/lo
__global__ void __launch_bounds__(256) transpose_split_kernel(
    const float* __restrict__ W, __nv_bfloat16* __restrict__ Th, __nv_bfloat16* __restrict__ Tl,
    int K, int N)
{
    __shared__ float tile[32][33];
    const int tx = threadIdx.x & 31, ty = threadIdx.x >> 5; // 32x8
    const int n0 = blockIdx.x * 32, k0 = blockIdx.y * 32;
    for (int dy = ty; dy < 32; dy += 8) {
        const int k = k0 + dy, n = n0 + tx;
        tile[dy][tx] = (k < K && n < N) ? W[(size_t)k * N + n] : 0.f;
    }
    __syncthreads();
    for (int dy = ty; dy < 32; dy += 8) {
        const int n = n0 + dy, k = k0 + tx;
        if (n < N && k < K) {
            const float v = tile[tx][dy];
            const __nv_bfloat16 h = __float2bfloat16(v);
            Th[(size_t)n * K + k] = h;
            Tl[(size_t)n * K + k] = __float2bfloat16(v - __bfloat162float(h));
        }
    }
}

__global__ void __launch_bounds__(256) split_feat_kernel(const float* __restrict__ F) {
    const size_t i = (size_t)blockIdx.x * 256 + threadIdx.x;
    if (i >= (size_t)NV * DD / 2) return;
    const float2 v = ((const float2*)F)[i];
    const __nv_bfloat16 h0 = __float2bfloat16(v.x);
    const __nv_bfloat16 h1 = __float2bfloat16(v.y);
    __nv_bfloat162 hp; hp.x = h0; hp.y = h1;
    __nv_bfloat162 lp;
    lp.x = __float2bfloat16(v.x - __bfloat162float(h0));
    lp.y = __float2bfloat16(v.y - __bfloat162float(h1));
    ((__nv_bfloat162*)g_Fhi)[i] = hp;
    ((__nv_bfloat162*)g_Flo)[i] = lp;
}

// ---------------- gather + mean + bias + relu -> H1 hi/lo --------------------
__global__ void __launch_bounds__(128) gather_mean_kernel(const int* __restrict__ faces,
                                                          const float* __restrict__ b1) {
    const int f = blockIdx.x;
    const int c4 = threadIdx.x;
    const int i0 = faces[f * 3 + 0];
    const int i1 = faces[f * 3 + 1];
    const int i2 = faces[f * 3 + 2];
    const float4* P4 = (const float4*)g_P;
    float4 v0 = P4[(size_t)i0 * 128 + c4];
    float4 v1 = P4[(size_t)i1 * 128 + c4];
    float4 v2 = P4[(size_t)i2 * 128 + c4];
    float4 bb = ((const float4*)b1)[c4];
    const float third = 1.f / 3.f;
    float o[4];
    o[0] = fmaxf((v0.x + v1.x + v2.x) * third + bb.x, 0.f);
    o[1] = fmaxf((v0.y + v1.y + v2.y) * third + bb.y, 0.f);
    o[2] = fmaxf((v0.z + v1.z + v2.z) * third + bb.z, 0.f);
    o[3] = fmaxf((v0.w + v1.w + v2.w) * third + bb.w, 0.f);
    __nv_bfloat16 h[4], l[4];
#pragma unroll
    for (int j = 0; j < 4; j++) {
        h[j] = __float2bfloat16(o[j]);
        l[j] = __float2bfloat16(o[j] - __bfloat162float(h[j]));
    }
    const size_t e = (size_t)f * DD + c4 * 4;
    __nv_bfloat162 hp0; hp0.x = h[0]; hp0.y = h[1];
    __nv_bfloat162 hp1; hp1.x = h[2]; hp1.y = h[3];
    __nv_bfloat162 lp0; lp0.x = l[0]; lp0.y = l[1];
    __nv_bfloat162 lp1; lp1.x = l[2]; lp1.y = l[3];
    *(__nv_bfloat162*)(g_H1hi + e) = hp0;
    *(__nv_bfloat162*)(g_H1hi + e + 2) = hp1;
    *(__nv_bfloat162*)(g_H1lo + e) = lp0;
    *(__nv_bfloat162*)(g_H1lo + e + 2) = lp1;
}

// ---------------- head: OUT12 = H3 @ W4 + b4  (warp per row) -----------------
__global__ void __launch_bounds__(256) head_kernel(const float* __restrict__ W4,
                                                   const float* __restrict__ b4) {
    __shared__ float sW[256 * 12];
    __shared__ float sb[12];
    const int tid = threadIdx.x;
    for (int i = tid; i < 256 * 12; i += 256) sW[i] = W4[i];
    if (tid < 12) sb[tid] = b4[tid];
    __syncthreads();
    const int warp = tid >> 5, lane = tid & 31;
    const int row = blockIdx.x * 8 + warp;
    if (row >= NF) return;
    const float* h = g_P + (size_t)row * 256;
    float hr[8];
#pragma unroll
    for (int i = 0; i < 8; i++) hr[i] = h[lane + 32 * i];
    float acc[12];
#pragma unroll
    for (int c = 0; c < 12; c++) acc[c] = 0.f;
#pragma unroll
    for (int i = 0; i < 8; i++) {
        const float hv = hr[i];
        const float* w = &sW[(lane + 32 * i) * 12];
#pragma unroll
        for (int c = 0; c < 12; c++) acc[c] = fmaf(hv, w[c], acc[c]);
    }
#pragma unroll
    for (int off = 16; off > 0; off >>= 1)
#pragma unroll
        for (int c = 0; c < 12; c++) acc[c] += __shfl_down_sync(0xffffffffu, acc[c], off);
    if (lane == 0) {
        float* o = g_OUT12 + (size_t)row * 12;
#pragma unroll
        for (int c = 0; c < 12; c++) o[c] = acc[c] + sb[c];
    }
}

__global__ void zero_kernel() {
    const int i = blockIdx.x * blockDim.x + threadIdx.x;
    if (i < NV * 3) g_sums[i] = 0.f;
    if (i < NV) g_cnt[i] = 0.f;
}

// ---------------- procrustes + transform + scatter ---------------------------
__device__ __forceinline__ void ortho_fallback(const float u[3], float o[3]) {
    const float ax = fabsf(u[0]), ay = fabsf(u[1]), az = fabsf(u[2]);
    float t0 = 0.f, t1 = 0.f, t2 = 0.f;
    if (ax <= ay && ax <= az) t0 = 1.f; else if (ay <= az) t1 = 1.f; else t2 = 1.f;
    const float d = t0 * u[0] + t1 * u[1] + t2 * u[2];
    o[0] = t0 - d * u[0]; o[1] = t1 - d * u[1]; o[2] = t2 - d * u[2];
    const float n = 1.f / sqrtf(o[0] * o[0] + o[1] * o[1] + o[2] * o[2]);
    o[0] *= n; o[1] *= n; o[2] *= n;
}

__global__ void __launch_bounds__(128) proc_kernel(
    const float* __restrict__ verts, const int* __restrict__ faces,
    float* __restrict__ out_tp, float* __restrict__ out_rot)
{
    const int f = blockIdx.x * 128 + threadIdx.x;
    if (f >= NF) return;
    const float* o = g_OUT12 + (size_t)f * 12;
    float m[3][3];
#pragma unroll
    for (int r = 0; r < 3; r++)
#pragma unroll
        for (int c = 0; c < 3; c++) m[r][c] = o[3 * r + c];
    const float tr0 = o[9], tr1 = o[10], tr2 = o[11];

    float Aa[3][3];
#pragma unroll
    for (int i = 0; i < 3; i++)
#pragma unroll
        for (int j = 0; j < 3; j++)
            Aa[i][j] = m[0][i] * m[0][j] + m[1][i] * m[1][j] + m[2][i] * m[2][j];

    float Vm[3][3] = {{1.f, 0.f, 0.f}, {0.f, 1.f, 0.f}, {0.f, 0.f, 1.f}};
    const int PP[3] = {0, 0, 1};
    const int QQ[3] = {1, 2, 2};
    for (int sweep = 0; sweep < 8; ++sweep) {
#pragma unroll
        for (int pi = 0; pi < 3; ++pi) {
            const int p = PP[pi], q = QQ[pi];
            const float apq = Aa[p][q];
            if (fabsf(apq) < 1e-38f) continue;
            const float tau = (Aa[q][q] - Aa[p][p]) / (2.f * apq);
            const float tt = copysignf(1.f, tau) / (fabsf(tau) + sqrtf(1.f + tau * tau));
            const float cc = 1.f / sqrtf(1.f + tt * tt);
            const float ss = tt * cc;
#pragma unroll
            for (int r = 0; r < 3; r++) {
                const float arp = Aa[r][p], arq = Aa[r][q];
                Aa[r][p] = cc * arp - ss * arq; Aa[r][q] = ss * arp + cc * arq;
            }
#pragma unroll
            for (int r = 0; r < 3; r++) {
                const float apr = Aa[p][r], aqr = Aa[q][r];
                Aa[p][r] = cc * apr - ss * aqr; Aa[q][r] = ss * apr + cc * aqr;
            }
#pragma unroll
            for (int r = 0; r < 3; r++) {
                const float vrp = Vm[r][p], vrq = Vm[r][q];
                Vm[r][p] = cc * vrp - ss * vrq; Vm[r][q] = ss * vrp + cc * vrq;
            }
        }
    }

    float dd[3] = {Aa[0][0], Aa[1][1], Aa[2][2]};
    int i0 = 0, i1 = 1, i2 = 2, tmp;
    if (dd[i0] < dd[i1]) { tmp = i0; i0 = i1; i1 = tmp; }
    if (dd[i0] < dd[i2]) { tmp = i0; i0 = i2; i2 = tmp; }
    if (dd[i1] < dd[i2]) { tmp = i1; i1 = i2; i2 = tmp; }
    const float v1[3] = {Vm[0][i0], Vm[1][i0], Vm[2][i0]};
    const float v2[3] = {Vm[0][i1], Vm[1][i1], Vm[2][i1]};
    const float v3[3] = {Vm[0][i2], Vm[1][i2], Vm[2][i2]};

    const float cx = v2[1] * v3[2] - v2[2] * v3[1];
    const float cy = v2[2] * v3[0] - v2[0] * v3[2];
    const float cz = v2[0] * v3[1] - v2[1] * v3[0];
    float s = v1[0] * cx + v1[1] * cy + v1[2] * cz;
    s = (s >= 0.f) ? 1.f : -1.f;

    float u1[3], u2[3];
#pragma unroll
    for (int r = 0; r < 3; r++)
        u1[r] = m[r][0] * v1[0] + m[r][1] * v1[1] + m[r][2] * v1[2];
    const float n1 = sqrtf(u1[0] * u1[0] + u1[1] * u1[1] + u1[2] * u1[2]);
    if (n1 > 1e-30f) { const float inv = 1.f / n1; u1[0] *= inv; u1[1] *= inv; u1[2] *= inv; }
    else { u1[0] = 1.f; u1[1] = 0.f; u1[2] = 0.f; }
#pragma unroll
    for (int r = 0; r < 3; r++)
        u2[r] = m[r][0] * v2[0] + m[r][1] * v2[1] + m[r][2] * v2[2];
    const float dp = u2[0] * u1[0] + u2[1] * u1[1] + u2[2] * u1[2];
    u2[0] -= dp * u1[0]; u2[1] -= dp * u1[1]; u2[2] -= dp * u1[2];
    const float n2 = sqrtf(u2[0] * u2[0] + u2[1] * u2[1] + u2[2] * u2[2]);
    if (n2 > 1e-30f) { const float inv = 1.f / n2; u2[0] *= inv; u2[1] *= inv; u2[2] *= inv; }
    else ortho_fallback(u1, u2);
    const float u3[3] = {u1[1] * u2[2] - u1[2] * u2[1],
                         u1[2] * u2[0] - u1[0] * u2[2],
                         u1[0] * u2[1] - u1[1] * u2[0]};

    float R[3][3];
#pragma unroll
    for (int r = 0; r < 3; r++) {
        R[r][0] = u1[r] * v1[0] + u2[r] * v2[0] + s * u3[r] * v3[0];
        R[r][1] = u1[r] * v1[1] + u2[r] * v2[1] + s * u3[r] * v3[1];
        R[r][2] = u1[r] * v1[2] + u2[r] * v2[2] + s * u3[r] * v3[2];
    }

    float* rot = out_rot + (size_t)f * 9;
#pragma unroll
    for (int r = 0; r < 3; r++) {
        rot[3 * r + 0] = R[r][0]; rot[3 * r + 1] = R[r][1]; rot[3 * r + 2] = R[r][2];
    }

    float* tp = out_tp + (size_t)f * 9;
#pragma unroll
    for (int i = 0; i < 3; i++) {
        const int v = faces[f * 3 + i];
        const float px = verts[v * 3 + 0], py = verts[v * 3 + 1], pz = verts[v * 3 + 2];
        const float x = px * R[0][0] + py * R[1][0] + pz * R[2][0] + tr0;
        const float y = px * R[0][1] + py * R[1][1] + pz * R[2][1] + tr1;
        const float z = px * R[0][2] + py * R[1][2] + pz * R[2][2] + tr2;
        tp[3 * i + 0] = x; tp[3 * i + 1] = y; tp[3 * i + 2] = z;
        atomicAdd(&g_sums[v * 3 + 0], x);
        atomicAdd(&g_sums[v * 3 + 1], y);
        atomicAdd(&g_sums[v * 3 + 2], z);
        atomicAdd(&g_cnt[v], 1.f);
    }
}

__global__ void __launch_bounds__(128) finalize_kernel(float* __restrict__ out_feat) {
    const int v = blockIdx.x * 128 + threadIdx.x;
    if (v >= NV) return;
    const float inv = 1.f / fmaxf(g_cnt[v], 1.f);
    out_feat[v * 3 + 0] = g_sums[v * 3 + 0] * inv;
    out_feat[v * 3 + 1] = g_sums[v * 3 + 1] * inv;
    out_feat[v * 3 + 2] = g_sums[v * 3 + 2] * inv;
}

// ---------------- launch -----------------------------------------------------
extern "C" void kernel_launch(void* const* d_in, const int* in_sizes, int n_in,
                              void* d_out, int out_size) {
    const float* verts    = (const float*)d_in[0];
    const float* features = (const float*)d_in[1];
    const int*   faces    = (const int*)d_in[2];
    const float* W1 = (const float*)d_in[3];
    const float* b1 = (const float*)d_in[4];
    const float* W2 = (const float*)d_in[5];
    const float* b2 = (const float*)d_in[6];
    const float* W3 = (const float*)d_in[7];
    const float* b3 = (const float*)d_in[8];
    const float* W4 = (const float*)d_in[9];
    const float* b4 = (const float*)d_in[10];

    float* out = (float*)d_out;
    float* out_feat = out;                          // (1, NV, 3)
    float* out_tp   = out + (size_t)NV * 3;         // (NF, 3, 3)
    float* out_rot  = out_tp + (size_t)NF * 9;      // (NF, 3, 3)

    static bool attr_done = false;
    if (!attr_done) {
        cudaFuncSetAttribute(gemm_mma_kernel<false, false>,
                             cudaFuncAttributeMaxDynamicSharedMemorySize, GSMEM_TOTAL);
        cudaFuncSetAttribute(gemm_mma_kernel<true, true>,
                             cudaFuncAttributeMaxDynamicSharedMemorySize, GSMEM_TOTAL);
        cudaFuncSetAttribute(gemm_mma_kernel<true, false>,
                             cudaFuncAttributeMaxDynamicSharedMemorySize, GSMEM_TOTAL);
        attr_done = true;
    }

    __nv_bfloat16 *Fhi, *Flo, *H1hi, *H1lo, *H2hi, *H2lo;
    __nv_bfloat16 *Wt1hi, *Wt1lo, *Wt2hi, *Wt2lo, *Wt3hi, *Wt3lo;
    float* Pp;
    cudaGetSymbolAddress((void**)&Fhi, g_Fhi);
    cudaGetSymbolAddress((void**)&Flo, g_Flo);
    cudaGetSymbolAddress((void**)&H1hi, g_H1hi);
    cudaGetSymbolAddress((void**)&H1lo, g_H1lo);
    cudaGetSymbolAddress((void**)&H2hi, g_H2hi);
    cudaGetSymbolAddress((void**)&H2lo, g_H2lo);
    cudaGetSymbolAddress((void**)&Wt1hi, g_Wt1hi);
    cudaGetSymbolAddress((void**)&Wt1lo, g_Wt1lo);
    cudaGetSymbolAddress((void**)&Wt2hi, g_Wt2hi);
    cudaGetSymbolAddress((void**)&Wt2lo, g_Wt2lo);
    cudaGetSymbolAddress((void**)&Wt3hi, g_Wt3hi);
    cudaGetSymbolAddress((void**)&Wt3lo, g_Wt3lo);
    cudaGetSymbolAddress((void**)&Pp, g_P);

    zero_kernel<<<(NV * 3 + 255) / 256, 256>>>();

    split_feat_kernel<<<(int)(((size_t)NV * DD / 2 + 255) / 256), 256>>>(features);
    transpose_split_kernel<<<dim3(512 / 32, 512 / 32), 256>>>(W1, Wt1hi, Wt1lo, 512, 512);
    transpose_split_kernel<<<dim3(512 / 32, 512 / 32), 256>>>(W2, Wt2hi, Wt2lo, 512, 512);
    transpose_split_kernel<<<dim3(256 / 32, 512 / 32), 256>>>(W3, Wt3hi, Wt3lo, 512, 256);

    // P = features @ W1 (fp32 out)
    gemm_mma_kernel<false, false><<<dim3(4, (NV + 127) / 128), 256, GSMEM_TOTAL>>>(
        Fhi, Flo, Wt1hi, Wt1lo, nullptr, Pp, nullptr, nullptr, NV, 512);

    // H1 = relu(mean(P[faces]) + b1) -> hi/lo
    gather_mean_kernel<<<NF, 128>>>(faces, b1);

    // H2 = relu(H1 @ W2 + b2) -> hi/lo
    gemm_mma_kernel<true, true><<<dim3(4, (NF + 127) / 128), 256, GSMEM_TOTAL>>>(
        H1hi, H1lo, Wt2hi, Wt2lo, b2, nullptr, H2hi, H2lo, NF, 512);

    // H3 = relu(H2 @ W3 + b3) -> fp32 into g_P
    gemm_mma_kernel<true, false><<<dim3(2, (NF + 127) / 128), 256, GSMEM_TOTAL>>>(
        H2hi, H2lo, Wt3hi, Wt3lo, b3, Pp, nullptr, nullptr, NF, 256);

    head_kernel<<<(NF + 7) / 8, 256>>>(W4, b4);
    proc_kernel<<<(NF + 127) / 128, 128>>>(verts, faces, out_tp, out_rot);
    finalize_kernel<<<(NV + 127) / 128, 128>>>(out_feat);
}

// round 10
// speedup vs baseline: 2.3340x; 1.1269x over previous
#include <cuda_runtime.h>
#include <cuda_bf16.h>
#include <math.h>
#include <stdint.h>

#define NV 100000
#define NF 200000
#define DD 512

// ---------------- scratch (device globals; no allocs allowed) ----------------
__device__ float g_P[(size_t)NV * DD];               // P = features@W1 (fp32); reused as H3 [NF,256] fp32
__device__ __nv_bfloat16 g_Fhi[(size_t)NV * DD];
__device__ __nv_bfloat16 g_Flo[(size_t)NV * DD];
__device__ __nv_bfloat16 g_H1hi[(size_t)NF * DD];
__device__ __nv_bfloat16 g_H1lo[(size_t)NF * DD];
__device__ __nv_bfloat16 g_H2hi[(size_t)NF * DD];
__device__ __nv_bfloat16 g_H2lo[(size_t)NF * DD];
__device__ __nv_bfloat16 g_Wt1hi[DD * DD], g_Wt1lo[DD * DD];   // [N,K] (transposed, K-major)
__device__ __nv_bfloat16 g_Wt2hi[DD * DD], g_Wt2lo[DD * DD];
__device__ __nv_bfloat16 g_Wt3hi[256 * DD], g_Wt3lo[256 * DD];
__device__ float g_OUT12[(size_t)NF * 12];
__device__ float g_sums[NV * 3];
__device__ float g_cnt[NV];

// ---------------- PTX helpers (arch-neutral: ldmatrix/mma.sync/cp.async) -----
static __device__ __forceinline__ uint32_t smem_u32(const void* p) {
    uint32_t a;
    asm("{ .reg .u64 t; cvta.to.shared.u64 t, %1; cvt.u32.u64 %0, t; }" : "=r"(a) : "l"(p));
    return a;
}

#define CP_ASYNC16(dst, src, sz) \
    asm volatile("cp.async.cg.shared.global [%0], [%1], 16, %2;" :: "r"(dst), "l"(src), "r"(sz))
#define CP_COMMIT() asm volatile("cp.async.commit_group;")
#define CP_WAIT1()  asm volatile("cp.async.wait_group 1;" ::: "memory")

#define LDSM4(r, addr) \
    asm volatile("ldmatrix.sync.aligned.m8n8.x4.shared.b16 {%0,%1,%2,%3}, [%4];" \
        : "=r"((r)[0]), "=r"((r)[1]), "=r"((r)[2]), "=r"((r)[3]) : "r"(addr))

#define MMA16816(d, a, b0, b1) \
    asm volatile("mma.sync.aligned.m16n8k16.row.col.f32.bf16.bf16.f32 " \
        "{%0,%1,%2,%3}, {%4,%5,%6,%7}, {%8,%9}, {%0,%1,%2,%3};" \
        : "+f"((d)[0]), "+f"((d)[1]), "+f"((d)[2]), "+f"((d)[3]) \
        : "r"((a)[0]), "r"((a)[1]), "r"((a)[2]), "r"((a)[3]), "r"(b0), "r"(b1))

// ---------------- split-bf16 GEMM via mma.sync --------------------------------
// C[M,N] = (A_hi+A_lo)[M,K] @ (B_hi+B_lo)^T, B stored [N,K] K-major.
// BM=128, BN=128, BK=32 bf16; 256 threads = 8 warps (4 m x 2 n); warp tile 32x64.
// Split: hi*hi + lo*hi + hi*lo (3 MMA terms).
// 3-stage cp.async pipeline, ONE __syncthreads per k-tile, 2 CTAs/SM.
// Stage = A_hi(8K) A_lo(8K) B_hi(8K) B_lo(8K) = 32KB; 3 stages = 96KB.

#define NSTAGE 3
#define STAGE_BYTES 32768
#define GSMEM_TOTAL (NSTAGE * STAGE_BYTES)

static __device__ __forceinline__ uint32_t sw_off(int r, int c) {
    return (uint32_t)(r * 64 + ((c ^ ((r >> 1) & 3)) << 4));
}

template<bool BIASRELU, bool SPLITOUT>
__global__ void __launch_bounds__(256, 2) gemm_mma_kernel(
    const __nv_bfloat16* __restrict__ A_hi, const __nv_bfloat16* __restrict__ A_lo,
    const __nv_bfloat16* __restrict__ B_hi, const __nv_bfloat16* __restrict__ B_lo,
    const float* __restrict__ bias,
    float* __restrict__ Cf, __nv_bfloat16* __restrict__ Chi, __nv_bfloat16* __restrict__ Clo,
    int M, int N)
{
    extern __shared__ char smem[];
    __shared__ float sbias[128];
    const uint32_t smem_base = smem_u32(smem);
    const int tid = threadIdx.x;
    const int wid = tid >> 5;
    const int lane = tid & 31;
    const int wm = wid & 3;           // 4 warps along M
    const int wn = wid >> 2;          // 2 warps along N
    const long brow = (long)blockIdx.y * 128;
    const long bcol = (long)blockIdx.x * 128;
    const int K = DD;

    if (BIASRELU && tid < 128) sbias[tid] = bias[bcol + tid];

    // ---- stage loader (cp.async) ----
    auto load_stage = [&](int kt, int st) {
        const int kc = kt * 32;
        const uint32_t sb = smem_base + st * STAGE_BYTES;
#pragma unroll
        for (int i = 0; i < 2; i++) {
            const int idx = tid * 2 + i;      // 0..511
            const int r = idx >> 2, c = idx & 3;
            const uint32_t so = sw_off(r, c);
            const long ga = brow + r;
            const int okA = (ga < M) ? 16 : 0;
            const size_t eA = (size_t)(okA ? ga : 0) * K + kc + c * 8;
            CP_ASYNC16(sb + so,          A_hi + eA, okA);
            CP_ASYNC16(sb + 8192 + so,   A_lo + eA, okA);
            const size_t eB = (size_t)(bcol + r) * K + kc + c * 8;
            CP_ASYNC16(sb + 16384 + so,  B_hi + eB, 16);
            CP_ASYNC16(sb + 24576 + so,  B_lo + eB, 16);
        }
    };

    float acc[2][8][4];
#pragma unroll
    for (int mt = 0; mt < 2; mt++)
#pragma unroll
        for (int nt = 0; nt < 8; nt++)
#pragma unroll
            for (int j = 0; j < 4; j++) acc[mt][nt][j] = 0.f;

    // prologue: 2 stages in flight
    load_stage(0, 0); CP_COMMIT();
    load_stage(1, 1); CP_COMMIT();

    const int NKT = K / 32;
    for (int kt = 0; kt < NKT; kt++) {
        CP_WAIT1();              // stage kt (group kt) complete
        __syncthreads();
        int st = kt; while (st >= NSTAGE) st -= NSTAGE;
        const uint32_t sA_hi = smem_base + st * STAGE_BYTES;
        const uint32_t sA_lo = sA_hi + 8192;
        const uint32_t sB_hi = sA_hi + 16384;
        const uint32_t sB_lo = sA_hi + 24576;

#pragma unroll
        for (int ks = 0; ks < 2; ks++) {
            uint32_t ah[2][4], al[2][4];
#pragma unroll
            for (int mt = 0; mt < 2; mt++) {
                const int r = wm * 32 + mt * 16 + (lane & 15);
                const int c = ks * 2 + (lane >> 4);
                const uint32_t so = sw_off(r, c);
                LDSM4(ah[mt], sA_hi + so);
                LDSM4(al[mt], sA_lo + so);
            }
            // B fragments scoped per 16-col group to cap live registers;
            // term-major inside keeps same-acc MMA dependency distance at 4.
#pragma unroll
            for (int np = 0; np < 4; np++) {
                uint32_t bh[4], bl[4];
                const int r = wn * 64 + np * 16 + (lane & 7) + (((lane >> 4) & 1) << 3);
                const int c = ks * 2 + ((lane >> 3) & 1);
                const uint32_t so = sw_off(r, c);
                LDSM4(bh, sB_hi + so);
                LDSM4(bl, sB_lo + so);
                // term 0: ah * bh
#pragma unroll
                for (int mt = 0; mt < 2; mt++)
#pragma unroll
                    for (int j = 0; j < 2; j++)
                        MMA16816(acc[mt][np * 2 + j], ah[mt], bh[j * 2], bh[j * 2 + 1]);
                // term 1: al * bh
#pragma unroll
                for (int mt = 0; mt < 2; mt++)
#pragma unroll
                    for (int j = 0; j < 2; j++)
                        MMA16816(acc[mt][np * 2 + j], al[mt], bh[j * 2], bh[j * 2 + 1]);
                // term 2: ah * bl
#pragma unroll
                for (int mt = 0; mt < 2; mt++)
#pragma unroll
                    for (int j = 0; j < 2; j++)
                        MMA16816(acc[mt][np * 2 + j], ah[mt], bl[j * 2], bl[j * 2 + 1]);
            }
        }
        // issue loads for stage kt+2 into slot (kt+2)%3 == (kt-1)%3 (safe:
        // all warps passed sync(kt), so compute(kt-1) on that slot is done).
        if (kt + 2 < NKT) { int s2 = kt + 2; while (s2 >= NSTAGE) s2 -= NSTAGE; load_stage(kt + 2, s2); }
        CP_COMMIT();             // commit every iteration keeps group math exact
    }

    // ---- epilogue ----
#pragma unroll
    for (int mt = 0; mt < 2; mt++) {
        const long r0 = brow + wm * 32 + mt * 16 + (lane >> 2);
        const long r1 = r0 + 8;
#pragma unroll
        for (int nt = 0; nt < 8; nt++) {
            const int coll = wn * 64 + nt * 8 + (lane & 3) * 2;   // block-local col
            const long col = bcol + coll;
            float v00 = acc[mt][nt][0], v01 = acc[mt][nt][1];
            float v10 = acc[mt][nt][2], v11 = acc[mt][nt][3];
            if (BIASRELU) {
                const float bb0 = sbias[coll], bb1 = sbias[coll + 1];
                v00 = fmaxf(v00 + bb0, 0.f); v01 = fmaxf(v01 + bb1, 0.f);
                v10 = fmaxf(v10 + bb0, 0.f); v11 = fmaxf(v11 + bb1, 0.f);
            }
            if (SPLITOUT) {
                if (r0 < M) {
                    const __nv_bfloat16 h0 = __float2bfloat16(v00);
                    const __nv_bfloat16 h1 = __float2bfloat16(v01);
                    __nv_bfloat162 hp; hp.x = h0; hp.y = h1;
                    __nv_bfloat162 lp;
                    lp.x = __float2bfloat16(v00 - __bfloat162float(h0));
                    lp.y = __float2bfloat16(v01 - __bfloat162float(h1));
                    *(__nv_bfloat162*)(Chi + (size_t)r0 * N + col) = hp;
                    *(__nv_bfloat162*)(Clo + (size_t)r0 * N + col) = lp;
                }
                if (r1 < M) {
                    const __nv_bfloat16 h0 = __float2bfloat16(v10);
                    const __nv_bfloat16 h1 = __float2bfloat16(v11);
                    __nv_bfloat162 hp; hp.x = h0; hp.y = h1;
                    __nv_bfloat162 lp;
                    lp.x = __float2bfloat16(v10 - __bfloat162float(h0));
                    lp.y = __float2bfloat16(v11 - __bfloat162float(h1));
                    *(__nv_bfloat162*)(Chi + (size_t)r1 * N + col) = hp;
                    *(__nv_bfloat162*)(Clo + (size_t)r1 * N + col) = lp;
                }
            } else {
                if (r0 < M) { float2 o; o.x = v00; o.y = v01; *(float2*)(Cf + (size_t)r0 * N + col) = o; }
                if (r1 < M) { float2 o; o.x = v10; o.y = v11; *(float2*)(Cf + (size_t)r1 * N + col) = o; }
            }
        }
    }
}

// ---------------- prep kernels ------------------------------------------------
// W[K,N] (row-major) -> Th/Tl[N,K] bf16 hi/lo
__global__ void __launch_bounds__(256) transpose_split_kernel(
    const float* __restrict__ W, __nv_bfloat16* __restrict__ Th, __nv_bfloat16* __restrict__ Tl,
    int K, int N)
{
    __shared__ float tile[32][33];
    const int tx = threadIdx.x & 31, ty = threadIdx.x >> 5; // 32x8
    const int n0 = blockIdx.x * 32, k0 = blockIdx.y * 32;
    for (int dy = ty; dy < 32; dy += 8) {
        const int k = k0 + dy, n = n0 + tx;
        tile[dy][tx] = (k < K && n < N) ? W[(size_t)k * N + n] : 0.f;
    }
    __syncthreads();
    for (int dy = ty; dy < 32; dy += 8) {
        const int n = n0 + dy, k = k0 + tx;
        if (n < N && k < K) {
            const float v = tile[tx][dy];
            const __nv_bfloat16 h = __float2bfloat16(v);
            Th[(size_t)n * K + k] = h;
            Tl[(size_t)n * K + k] = __float2bfloat16(v - __bfloat162float(h));
        }
    }
}

__global__ void __launch_bounds__(256) split_feat_kernel(const float* __restrict__ F) {
    const size_t i = (size_t)blockIdx.x * 256 + threadIdx.x;
    if (i >= (size_t)NV * DD / 2) return;
    const float2 v = ((const float2*)F)[i];
    const __nv_bfloat16 h0 = __float2bfloat16(v.x);
    const __nv_bfloat16 h1 = __float2bfloat16(v.y);
    __nv_bfloat162 hp; hp.x = h0; hp.y = h1;
    __nv_bfloat162 lp;
    lp.x = __float2bfloat16(v.x - __bfloat162float(h0));
    lp.y = __float2bfloat16(v.y - __bfloat162float(h1));
    ((__nv_bfloat162*)g_Fhi)[i] = hp;
    ((__nv_bfloat162*)g_Flo)[i] = lp;
}

// ---------------- gather + mean + bias + relu -> H1 hi/lo --------------------
__global__ void __launch_bounds__(128) gather_mean_kernel(const int* __restrict__ faces,
                                                          const float* __restrict__ b1) {
    const int f = blockIdx.x;
    const int c4 = threadIdx.x;
    const int i0 = faces[f * 3 + 0];
    const int i1 = faces[f * 3 + 1];
    const int i2 = faces[f * 3 + 2];
    const float4* P4 = (const float4*)g_P;
    float4 v0 = P4[(size_t)i0 * 128 + c4];
    float4 v1 = P4[(size_t)i1 * 128 + c4];
    float4 v2 = P4[(size_t)i2 * 128 + c4];
    float4 bb = ((const float4*)b1)[c4];
    const float third = 1.f / 3.f;
    float o[4];
    o[0] = fmaxf((v0.x + v1.x + v2.x) * third + bb.x, 0.f);
    o[1] = fmaxf((v0.y + v1.y + v2.y) * third + bb.y, 0.f);
    o[2] = fmaxf((v0.z + v1.z + v2.z) * third + bb.z, 0.f);
    o[3] = fmaxf((v0.w + v1.w + v2.w) * third + bb.w, 0.f);
    __nv_bfloat16 h[4], l[4];
#pragma unroll
    for (int j = 0; j < 4; j++) {
        h[j] = __float2bfloat16(o[j]);
        l[j] = __float2bfloat16(o[j] - __bfloat162float(h[j]));
    }
    const size_t e = (size_t)f * DD + c4 * 4;
    __nv_bfloat162 hp0; hp0.x = h[0]; hp0.y = h[1];
    __nv_bfloat162 hp1; hp1.x = h[2]; hp1.y = h[3];
    __nv_bfloat162 lp0; lp0.x = l[0]; lp0.y = l[1];
    __nv_bfloat162 lp1; lp1.x = l[2]; lp1.y = l[3];
    *(__nv_bfloat162*)(g_H1hi + e) = hp0;
    *(__nv_bfloat162*)(g_H1hi + e + 2) = hp1;
    *(__nv_bfloat162*)(g_H1lo + e) = lp0;
    *(__nv_bfloat162*)(g_H1lo + e + 2) = lp1;
}

// ---------------- head: OUT12 = H3 @ W4 + b4  (warp per row) -----------------
__global__ void __launch_bounds__(256) head_kernel(const float* __restrict__ W4,
                                                   const float* __restrict__ b4) {
    __shared__ float sW[256 * 12];
    __shared__ float sb[12];
    const int tid = threadIdx.x;
    for (int i = tid; i < 256 * 12; i += 256) sW[i] = W4[i];
    if (tid < 12) sb[tid] = b4[tid];
    __syncthreads();
    const int warp = tid >> 5, lane = tid & 31;
    const int row = blockIdx.x * 8 + warp;
    if (row >= NF) return;
    const float* h = g_P + (size_t)row * 256;
    float hr[8];
#pragma unroll
    for (int i = 0; i < 8; i++) hr[i] = h[lane + 32 * i];
    float acc[12];
#pragma unroll
    for (int c = 0; c < 12; c++) acc[c] = 0.f;
#pragma unroll
    for (int i = 0; i < 8; i++) {
        const float hv = hr[i];
        const float* w = &sW[(lane + 32 * i) * 12];
#pragma unroll
        for (int c = 0; c < 12; c++) acc[c] = fmaf(hv, w[c], acc[c]);
    }
#pragma unroll
    for (int off = 16; off > 0; off >>= 1)
#pragma unroll
        for (int c = 0; c < 12; c++) acc[c] += __shfl_down_sync(0xffffffffu, acc[c], off);
    if (lane == 0) {
        float* o = g_OUT12 + (size_t)row * 12;
#pragma unroll
        for (int c = 0; c < 12; c++) o[c] = acc[c] + sb[c];
    }
}

__global__ void zero_kernel() {
    const int i = blockIdx.x * blockDim.x + threadIdx.x;
    if (i < NV * 3) g_sums[i] = 0.f;
    if (i < NV) g_cnt[i] = 0.f;
}

// ---------------- procrustes + transform + scatter ---------------------------
__device__ __forceinline__ void ortho_fallback(const float u[3], float o[3]) {
    const float ax = fabsf(u[0]), ay = fabsf(u[1]), az = fabsf(u[2]);
    float t0 = 0.f, t1 = 0.f, t2 = 0.f;
    if (ax <= ay && ax <= az) t0 = 1.f; else if (ay <= az) t1 = 1.f; else t2 = 1.f;
    const float d = t0 * u[0] + t1 * u[1] + t2 * u[2];
    o[0] = t0 - d * u[0]; o[1] = t1 - d * u[1]; o[2] = t2 - d * u[2];
    const float n = 1.f / sqrtf(o[0] * o[0] + o[1] * o[1] + o[2] * o[2]);
    o[0] *= n; o[1] *= n; o[2] *= n;
}

__global__ void __launch_bounds__(128) proc_kernel(
    const float* __restrict__ verts, const int* __restrict__ faces,
    float* __restrict__ out_tp, float* __restrict__ out_rot)
{
    const int f = blockIdx.x * 128 + threadIdx.x;
    if (f >= NF) return;
    const float* o = g_OUT12 + (size_t)f * 12;
    float m[3][3];
#pragma unroll
    for (int r = 0; r < 3; r++)
#pragma unroll
        for (int c = 0; c < 3; c++) m[r][c] = o[3 * r + c];
    const float tr0 = o[9], tr1 = o[10], tr2 = o[11];

    float Aa[3][3];
#pragma unroll
    for (int i = 0; i < 3; i++)
#pragma unroll
        for (int j = 0; j < 3; j++)
            Aa[i][j] = m[0][i] * m[0][j] + m[1][i] * m[1][j] + m[2][i] * m[2][j];

    float Vm[3][3] = {{1.f, 0.f, 0.f}, {0.f, 1.f, 0.f}, {0.f, 0.f, 1.f}};
    const int PP[3] = {0, 0, 1};
    const int QQ[3] = {1, 2, 2};
    for (int sweep = 0; sweep < 8; ++sweep) {
#pragma unroll
        for (int pi = 0; pi < 3; ++pi) {
            const int p = PP[pi], q = QQ[pi];
            const float apq = Aa[p][q];
            if (fabsf(apq) < 1e-38f) continue;
            const float tau = (Aa[q][q] - Aa[p][p]) / (2.f * apq);
            const float tt = copysignf(1.f, tau) / (fabsf(tau) + sqrtf(1.f + tau * tau));
            const float cc = 1.f / sqrtf(1.f + tt * tt);
            const float ss = tt * cc;
#pragma unroll
            for (int r = 0; r < 3; r++) {
                const float arp = Aa[r][p], arq = Aa[r][q];
                Aa[r][p] = cc * arp - ss * arq; Aa[r][q] = ss * arp + cc * arq;
            }
#pragma unroll
            for (int r = 0; r < 3; r++) {
                const float apr = Aa[p][r], aqr = Aa[q][r];
                Aa[p][r] = cc * apr - ss * aqr; Aa[q][r] = ss * apr + cc * aqr;
            }
#pragma unroll
            for (int r = 0; r < 3; r++) {
                const float vrp = Vm[r][p], vrq = Vm[r][q];
                Vm[r][p] = cc * vrp - ss * vrq; Vm[r][q] = ss * vrp + cc * vrq;
            }
        }
    }

    float dd[3] = {Aa[0][0], Aa[1][1], Aa[2][2]};
    int i0 = 0, i1 = 1, i2 = 2, tmp;
    if (dd[i0] < dd[i1]) { tmp = i0; i0 = i1; i1 = tmp; }
    if (dd[i0] < dd[i2]) { tmp = i0; i0 = i2; i2 = tmp; }
    if (dd[i1] < dd[i2]) { tmp = i1; i1 = i2; i2 = tmp; }
    const float v1[3] = {Vm[0][i0], Vm[1][i0], Vm[2][i0]};
    const float v2[3] = {Vm[0][i1], Vm[1][i1], Vm[2][i1]};
    const float v3[3] = {Vm[0][i2], Vm[1][i2], Vm[2][i2]};

    const float cx = v2[1] * v3[2] - v2[2] * v3[1];
    const float cy = v2[2] * v3[0] - v2[0] * v3[2];
    const float cz = v2[0] * v3[1] - v2[1] * v3[0];
    float s = v1[0] * cx + v1[1] * cy + v1[2] * cz;
    s = (s >= 0.f) ? 1.f : -1.f;

    float u1[3], u2[3];
#pragma unroll
    for (int r = 0; r < 3; r++)
        u1[r] = m[r][0] * v1[0] + m[r][1] * v1[1] + m[r][2] * v1[2];
    const float n1 = sqrtf(u1[0] * u1[0] + u1[1] * u1[1] + u1[2] * u1[2]);
    if (n1 > 1e-30f) { const float inv = 1.f / n1; u1[0] *= inv; u1[1] *= inv; u1[2] *= inv; }
    else { u1[0] = 1.f; u1[1] = 0.f; u1[2] = 0.f; }
#pragma unroll
    for (int r = 0; r < 3; r++)
        u2[r] = m[r][0] * v2[0] + m[r][1] * v2[1] + m[r][2] * v2[2];
    const float dp = u2[0] * u1[0] + u2[1] * u1[1] + u2[2] * u1[2];
    u2[0] -= dp * u1[0]; u2[1] -= dp * u1[1]; u2[2] -= dp * u1[2];
    const float n2 = sqrtf(u2[0] * u2[0] + u2[1] * u2[1] + u2[2] * u2[2]);
    if (n2 > 1e-30f) { const float inv = 1.f / n2; u2[0] *= inv; u2[1] *= inv; u2[2] *= inv; }
    else ortho_fallback(u1, u2);
    const float u3[3] = {u1[1] * u2[2] - u1[2] * u2[1],
                         u1[2] * u2[0] - u1[0] * u2[2],
                         u1[0] * u2[1] - u1[1] * u2[0]};

    float R[3][3];
#pragma unroll
    for (int r = 0; r < 3; r++) {
        R[r][0] = u1[r] * v1[0] + u2[r] * v2[0] + s * u3[r] * v3[0];
        R[r][1] = u1[r] * v1[1] + u2[r] * v2[1] + s * u3[r] * v3[1];
        R[r][2] = u1[r] * v1[2] + u2[r] * v2[2] + s * u3[r] * v3[2];
    }

    float* rot = out_rot + (size_t)f * 9;
#pragma unroll
    for (int r = 0; r < 3; r++) {
        rot[3 * r + 0] = R[r][0]; rot[3 * r + 1] = R[r][1]; rot[3 * r + 2] = R[r][2];
    }

    float* tp = out_tp + (size_t)f * 9;
#pragma unroll
    for (int i = 0; i < 3; i++) {
        const int v = faces[f * 3 + i];
        const float px = verts[v * 3 + 0], py = verts[v * 3 + 1], pz = verts[v * 3 + 2];
        const float x = px * R[0][0] + py * R[1][0] + pz * R[2][0] + tr0;
        const float y = px * R[0][1] + py * R[1][1] + pz * R[2][1] + tr1;
        const float z = px * R[0][2] + py * R[1][2] + pz * R[2][2] + tr2;
        tp[3 * i + 0] = x; tp[3 * i + 1] = y; tp[3 * i + 2] = z;
        atomicAdd(&g_sums[v * 3 + 0], x);
        atomicAdd(&g_sums[v * 3 + 1], y);
        atomicAdd(&g_sums[v * 3 + 2], z);
        atomicAdd(&g_cnt[v], 1.f);
    }
}

__global__ void __launch_bounds__(128) finalize_kernel(float* __restrict__ out_feat) {
    const int v = blockIdx.x * 128 + threadIdx.x;
    if (v >= NV) return;
    const float inv = 1.f / fmaxf(g_cnt[v], 1.f);
    out_feat[v * 3 + 0] = g_sums[v * 3 + 0] * inv;
    out_feat[v * 3 + 1] = g_sums[v * 3 + 1] * inv;
    out_feat[v * 3 + 2] = g_sums[v * 3 + 2] * inv;
}

// ---------------- launch -----------------------------------------------------
extern "C" void kernel_launch(void* const* d_in, const int* in_sizes, int n_in,
                              void* d_out, int out_size) {
    const float* verts    = (const float*)d_in[0];
    const float* features = (const float*)d_in[1];
    const int*   faces    = (const int*)d_in[2];
    const float* W1 = (const float*)d_in[3];
    const float* b1 = (const float*)d_in[4];
    const float* W2 = (const float*)d_in[5];
    const float* b2 = (const float*)d_in[6];
    const float* W3 = (const float*)d_in[7];
    const float* b3 = (const float*)d_in[8];
    const float* W4 = (const float*)d_in[9];
    const float* b4 = (const float*)d_in[10];

    float* out = (float*)d_out;
    float* out_feat = out;                          // (1, NV, 3)
    float* out_tp   = out + (size_t)NV * 3;         // (NF, 3, 3)
    float* out_rot  = out_tp + (size_t)NF * 9;      // (NF, 3, 3)

    static bool attr_done = false;
    if (!attr_done) {
        cudaFuncSetAttribute(gemm_mma_kernel<false, false>,
                             cudaFuncAttributeMaxDynamicSharedMemorySize, GSMEM_TOTAL);
        cudaFuncSetAttribute(gemm_mma_kernel<true, true>,
                             cudaFuncAttributeMaxDynamicSharedMemorySize, GSMEM_TOTAL);
        cudaFuncSetAttribute(gemm_mma_kernel<true, false>,
                             cudaFuncAttributeMaxDynamicSharedMemorySize, GSMEM_TOTAL);
        attr_done = true;
    }

    __nv_bfloat16 *Fhi, *Flo, *H1hi, *H1lo, *H2hi, *H2lo;
    __nv_bfloat16 *Wt1hi, *Wt1lo, *Wt2hi, *Wt2lo, *Wt3hi, *Wt3lo;
    float* Pp;
    cudaGetSymbolAddress((void**)&Fhi, g_Fhi);
    cudaGetSymbolAddress((void**)&Flo, g_Flo);
    cudaGetSymbolAddress((void**)&H1hi, g_H1hi);
    cudaGetSymbolAddress((void**)&H1lo, g_H1lo);
    cudaGetSymbolAddress((void**)&H2hi, g_H2hi);
    cudaGetSymbolAddress((void**)&H2lo, g_H2lo);
    cudaGetSymbolAddress((void**)&Wt1hi, g_Wt1hi);
    cudaGetSymbolAddress((void**)&Wt1lo, g_Wt1lo);
    cudaGetSymbolAddress((void**)&Wt2hi, g_Wt2hi);
    cudaGetSymbolAddress((void**)&Wt2lo, g_Wt2lo);
    cudaGetSymbolAddress((void**)&Wt3hi, g_Wt3hi);
    cudaGetSymbolAddress((void**)&Wt3lo, g_Wt3lo);
    cudaGetSymbolAddress((void**)&Pp, g_P);

    zero_kernel<<<(NV * 3 + 255) / 256, 256>>>();

    split_feat_kernel<<<(int)(((size_t)NV * DD / 2 + 255) / 256), 256>>>(features);
    transpose_split_kernel<<<dim3(512 / 32, 512 / 32), 256>>>(W1, Wt1hi, Wt1lo, 512, 512);
    transpose_split_kernel<<<dim3(512 / 32, 512 / 32), 256>>>(W2, Wt2hi, Wt2lo, 512, 512);
    transpose_split_kernel<<<dim3(256 / 32, 512 / 32), 256>>>(W3, Wt3hi, Wt3lo, 512, 256);

    // P = features @ W1 (fp32 out)
    gemm_mma_kernel<false, false><<<dim3(4, (NV + 127) / 128), 256, GSMEM_TOTAL>>>(
        Fhi, Flo, Wt1hi, Wt1lo, nullptr, Pp, nullptr, nullptr, NV, 512);

    // H1 = relu(mean(P[faces]) + b1) -> hi/lo
    gather_mean_kernel<<<NF, 128>>>(faces, b1);

    // H2 = relu(H1 @ W2 + b2) -> hi/lo
    gemm_mma_kernel<true, true><<<dim3(4, (NF + 127) / 128), 256, GSMEM_TOTAL>>>(
        H1hi, H1lo, Wt2hi, Wt2lo, b2, nullptr, H2hi, H2lo, NF, 512);

    // H3 = relu(H2 @ W3 + b3) -> fp32 into g_P
    gemm_mma_kernel<true, false><<<dim3(2, (NF + 127) / 128), 256, GSMEM_TOTAL>>>(
        H2hi, H2lo, Wt3hi, Wt3lo, b3, Pp, nullptr, nullptr, NF, 256);

    head_kernel<<<(NF + 7) / 8, 256>>>(W4, b4);
    proc_kernel<<<(NF + 127) / 128, 128>>>(verts, faces, out_tp, out_rot);
    finalize_kernel<<<(NV + 127) / 128, 128>>>(out_feat);
}